// round 13
// baseline (speedup 1.0000x reference)
#include <cuda_runtime.h>
#include <cuda_fp16.h>
#include <math.h>
#include <stdint.h>

// Problem constants
#define FEATD 256
#define HIDD  256
#define NHEAD 4
#define DHEAD 64
#define BATCH 4
#define SEQ   2048
#define TOK   (BATCH * SEQ)      // 8192 tokens per stream

// ---------------------------------------------------------------------------
// Scratch
// ---------------------------------------------------------------------------
__device__ float g_scratch[33554432];
#define OFS 2097152               // 8192*256 elements

// ---------------------------------------------------------------------------
// helpers
// ---------------------------------------------------------------------------
__device__ __forceinline__ uint32_t packh2(float a, float b) {
    __half2 h = __floats2half2_rn(a, b);
    return *reinterpret_cast<uint32_t*>(&h);
}

__device__ __forceinline__ void mma16(float d[4], const uint32_t a[4],
                                      const uint32_t b[2], const float c[4]) {
    asm volatile(
        "mma.sync.aligned.m16n8k16.row.col.f32.f16.f16.f32 "
        "{%0,%1,%2,%3},{%4,%5,%6,%7},{%8,%9},{%10,%11,%12,%13};\n"
        : "=f"(d[0]), "=f"(d[1]), "=f"(d[2]), "=f"(d[3])
        : "r"(a[0]), "r"(a[1]), "r"(a[2]), "r"(a[3]),
          "r"(b[0]), "r"(b[1]),
          "f"(c[0]), "f"(c[1]), "f"(c[2]), "f"(c[3]));
}

#define CP16(dst_u32, src_ptr) \
    asm volatile("cp.async.cg.shared.global [%0], [%1], 16;\n" :: "r"(dst_u32), "l"(src_ptr))
#define CP_COMMIT() asm volatile("cp.async.commit_group;\n" ::)
#define CP_WAIT(n)  asm volatile("cp.async.wait_group %0;\n" :: "n"(n))

#define LDSM4(r0, r1, r2, r3, addr) \
    asm volatile("ldmatrix.sync.aligned.m8n8.x4.shared.b16 {%0,%1,%2,%3},[%4];" \
        : "=r"(r0), "=r"(r1), "=r"(r2), "=r"(r3) : "r"(addr))
#define LDSM4T(r0, r1, r2, r3, addr) \
    asm volatile("ldmatrix.sync.aligned.m8n8.x4.trans.shared.b16 {%0,%1,%2,%3},[%4];" \
        : "=r"(r0), "=r"(r1), "=r"(r2), "=r"(r3) : "r"(addr))

// ---------------------------------------------------------------------------
// One-shot fp32 -> fp16 conversion: x0, x1, Wqk, Wv, W2.
// total float4 = 524288+524288+16384+16384+32768 = 1114112 = 4352*256
// ---------------------------------------------------------------------------
__global__ __launch_bounds__(256)
void f2h_all(const float* __restrict__ x0, const float* __restrict__ x1,
             const float* __restrict__ Wqk, const float* __restrict__ Wv,
             const float* __restrict__ W2,
             __half* xh0, __half* xh1, __half* Wqkh, __half* Wvh, __half* W2h)
{
    int i = blockIdx.x * 256 + threadIdx.x;
    const float* s; __half* d; int off;
    if      (i < 524288)  { s = x0;  d = xh0;  off = i; }
    else if (i < 1048576) { s = x1;  d = xh1;  off = i - 524288; }
    else if (i < 1064960) { s = Wqk; d = Wqkh; off = i - 1048576; }
    else if (i < 1081344) { s = Wv;  d = Wvh;  off = i - 1064960; }
    else                  { s = W2;  d = W2h;  off = i - 1081344; }
    float4 v = ((const float4*)s)[off];
    uint2 u;
    u.x = packh2(v.x, v.y);
    u.y = packh2(v.z, v.w);
    ((uint2*)d)[off] = u;
}

// ---------------------------------------------------------------------------
// Fold Wp into W1 (fp32 math, per-call, deterministic):
//   W1m'[n,c] = sum_j W1[n,256+j] * Wp[j*256+c]   -> W1h[n*512+256+c] (fp16)
//   W1h[n*512+c] = fp16(W1[n*512+c])              (lo half pass-through)
//   b1p[n] = b1[n] + sum_j W1[n,256+j] * bp[j]
// ---------------------------------------------------------------------------
__global__ __launch_bounds__(256)
void fold_w1(const float* __restrict__ W1, const float* __restrict__ Wp,
             const float* __restrict__ bp, const float* __restrict__ b1,
             __half* __restrict__ W1h, float* __restrict__ b1p)
{
    __shared__ float w1s[8][256];
    __shared__ float red[8][8];
    const int c = threadIdx.x;
    const int n0 = blockIdx.x * 8;

#pragma unroll
    for (int r = 0; r < 8; r++) {
        const size_t row = (size_t)(n0 + r) * 512;
        W1h[row + c] = __float2half(W1[row + c]);       // lo half
        w1s[r][c] = W1[row + 256 + c];                  // W1m row
    }
    __syncthreads();

    float pb[8], acc[8];
#pragma unroll
    for (int r = 0; r < 8; r++) { pb[r] = w1s[r][c] * bp[c]; acc[r] = 0.f; }

    for (int j = 0; j < 256; j++) {
        float wp = Wp[j * 256 + c];                     // coalesced row
#pragma unroll
        for (int r = 0; r < 8; r++) acc[r] = fmaf(w1s[r][j], wp, acc[r]);
    }
#pragma unroll
    for (int r = 0; r < 8; r++)
        W1h[(size_t)(n0 + r) * 512 + 256 + c] = __float2half(acc[r]);

    const int lane = c & 31, w = c >> 5;
#pragma unroll
    for (int r = 0; r < 8; r++) {
        float v = pb[r];
#pragma unroll
        for (int o = 16; o > 0; o >>= 1) v += __shfl_xor_sync(0xffffffffu, v, o);
        if (lane == 0) red[w][r] = v;
    }
    __syncthreads();
    if (c < 8) {
        float s = b1[n0 + c];
#pragma unroll
        for (int w2 = 0; w2 < 8; w2++) s += red[w2][c];
        b1p[n0 + c] = s;
    }
}

// ---------------------------------------------------------------------------
// fp16 tensor-core GEMM — R11's proven simple ldmatrix loop (the R12
// fragment-pipelined variant blew the register budget and regressed; revert).
// 3-slot cp.async pipeline, BK=32, one barrier per stage.
// MODE 0:+bias  2:+bias+res(fp32 out)  3: fused QKV epilogue.
// ---------------------------------------------------------------------------
#define GSTRH 40
#define GEMM_SMEM (3 * 2 * 128 * GSTRH * 2)

template<int MODE, int OUTH>
__global__ __launch_bounds__(256)
void gemm_tc(const __half* __restrict__ Alo0, const __half* __restrict__ Alo1,
             const __half* __restrict__ Ahi0, const __half* __restrict__ Ahi1,
             int Klo, int lda_lo, int lda_hi,
             const __half* __restrict__ W,
             const float* __restrict__ bias,
             const float* __restrict__ res0, const float* __restrict__ res1,
             void* __restrict__ C0v, void* __restrict__ C1v,
             void* __restrict__ D0v, void* __restrict__ D1v,
             int N, int K, float scale)
{
    extern __shared__ __half hsm[];
    __half* As = hsm;                           // [slot][128][GSTRH]
    __half* Ws = hsm + 3 * 128 * GSTRH;

    const int tid  = threadIdx.x;
    const int warp = tid >> 5, lane = tid & 31;
    const int g = lane >> 2, tg = lane & 3;
    const int wm = warp >> 1, wn = warp & 1;
    const int m0g = blockIdx.y * 128;
    const int stream = (m0g >= TOK) ? 1 : 0;
    const int m0 = m0g - stream * TOK;
    const int n0 = blockIdx.x * 128;

    const __half* __restrict__ Alo = stream ? Alo1 : Alo0;
    const __half* __restrict__ Ahi = stream ? Ahi1 : Ahi0;

    const int rl = tid >> 1;
    const int cl = (tid & 1) << 4;

    const int t8 = lane >> 3, rw = lane & 7;
    const int aRow = ((t8 & 1) << 3) + rw, aCol = (t8 >> 1) << 3;
    const int bRow = ((t8 >> 1) << 3) + rw, bCol = (t8 & 1) << 3;

    const int nst = K / 32;

    auto load_stage = [&](int ks, int slot) {
        const int kbase = ks * 32;
        const __half* Ab; int lda, ka;
        if (kbase < Klo) { Ab = Alo; lda = lda_lo; ka = kbase; }
        else             { Ab = Ahi; lda = lda_hi; ka = kbase - Klo; }
        __half* asl = As + (slot * 128 + rl) * GSTRH + cl;
        __half* wsl = Ws + (slot * 128 + rl) * GSTRH + cl;
        const __half* ag = Ab + (size_t)(m0 + rl) * lda + ka + cl;
        const __half* wg = W + (size_t)(n0 + rl) * K + kbase + cl;
        uint32_t d;
        d = (uint32_t)__cvta_generic_to_shared(asl);     CP16(d, ag);
        d = (uint32_t)__cvta_generic_to_shared(asl + 8); CP16(d, ag + 8);
        d = (uint32_t)__cvta_generic_to_shared(wsl);     CP16(d, wg);
        d = (uint32_t)__cvta_generic_to_shared(wsl + 8); CP16(d, wg + 8);
        CP_COMMIT();
    };

    float acc[2][8][4];
#pragma unroll
    for (int mi = 0; mi < 2; mi++)
#pragma unroll
        for (int ni = 0; ni < 8; ni++)
#pragma unroll
            for (int r = 0; r < 4; r++) acc[mi][ni][r] = 0.f;

    load_stage(0, 0);
    load_stage(1, 1);

    for (int ks = 0; ks < nst; ks++) {
        CP_WAIT(1);
        __syncthreads();
        if (ks + 2 < nst) load_stage(ks + 2, (ks + 2) % 3);
        else              CP_COMMIT();

        const int s = ks % 3;
        const __half* as = As + (size_t)s * 128 * GSTRH;
        const __half* ws = Ws + (size_t)s * 128 * GSTRH;
#pragma unroll
        for (int kk = 0; kk < 2; kk++) {
            const int kb = kk * 16;
            uint32_t af[2][4];
#pragma unroll
            for (int mi = 0; mi < 2; mi++) {
                uint32_t addr = (uint32_t)__cvta_generic_to_shared(
                    &as[(wm * 32 + mi * 16 + aRow) * GSTRH + kb + aCol]);
                LDSM4(af[mi][0], af[mi][1], af[mi][2], af[mi][3], addr);
            }
#pragma unroll
            for (int np = 0; np < 4; np++) {
                uint32_t b0, b1x, b2, b3;
                uint32_t addr = (uint32_t)__cvta_generic_to_shared(
                    &ws[(wn * 64 + np * 16 + bRow) * GSTRH + kb + bCol]);
                LDSM4(b0, b1x, b2, b3, addr);
                uint32_t bfa[2] = {b0, b1x}, bfb[2] = {b2, b3};
#pragma unroll
                for (int mi = 0; mi < 2; mi++) {
                    mma16(acc[mi][2*np    ], af[mi], bfa, acc[mi][2*np    ]);
                    mma16(acc[mi][2*np + 1], af[mi], bfb, acc[mi][2*np + 1]);
                }
            }
        }
    }

    const float* __restrict__ res = stream ? res1 : res0;
    const float* bias_eff = bias;
    float sc_eff = scale;
    __half* Cq = nullptr;
    int nstride = N;
    if (MODE == 3) {
        const int side = (n0 >= 256);
        sc_eff = side ? 1.f : scale;
        bias_eff = side ? (res0 - 256) : bias;     // res0 carries bias2 (bv)
        if (side) Cq = (__half*)((stream ? (__half*)D1v : (__half*)D0v) - 256);
        else      Cq = stream ? (__half*)C1v : (__half*)C0v;
        nstride = 256;
    }

#pragma unroll
    for (int mi = 0; mi < 2; mi++) {
#pragma unroll
        for (int rr = 0; rr < 2; rr++) {
            const int m = m0 + wm * 32 + mi * 16 + g + rr * 8;
#pragma unroll
            for (int ni = 0; ni < 8; ni++) {
                const int c = n0 + wn * 64 + ni * 8 + 2 * tg;
                float2 bb = *(const float2*)&bias_eff[c];
                float v0 = (acc[mi][ni][rr * 2 + 0] + bb.x) * sc_eff;
                float v1 = (acc[mi][ni][rr * 2 + 1] + bb.y) * sc_eff;
                if (MODE == 2) {
                    float2 rv = *(const float2*)&res[(size_t)m * N + c];
                    v0 += rv.x; v1 += rv.y;
                }
                if (MODE == 3) {
                    *(uint32_t*)&Cq[(size_t)m * nstride + c] = packh2(v0, v1);
                } else if (OUTH) {
                    __half* C = stream ? (__half*)C1v : (__half*)C0v;
                    *(uint32_t*)&C[(size_t)m * N + c] = packh2(v0, v1);
                } else {
                    float* C = stream ? (float*)C1v : (float*)C0v;
                    *(float2*)&C[(size_t)m * N + c] = make_float2(v0, v1);
                }
            }
        }
    }
}

// ---------------------------------------------------------------------------
// fp16 tensor-core flash attention — R12's version, MEASURED 121us @47.6%
// tensor: pipelined K/V fragment loads, hoisted first V ldmatrix over exp2.
// ---------------------------------------------------------------------------
#define ATQ 128
#define ATK 64
#define KSTR 72

__global__ __launch_bounds__(256, 2)
void attn_tc(const __half* __restrict__ qk0, const __half* __restrict__ qk1,
             const __half* __restrict__ v0m, const __half* __restrict__ v1m,
             __half* __restrict__ m0m, __half* __restrict__ m1m)
{
    __shared__ __align__(16) __half Ks[2][ATK][KSTR];
    __shared__ __align__(16) __half Vs[2][ATK][KSTR];

    const int tid  = threadIdx.x;
    const int warp = tid >> 5, lane = tid & 31;
    const int g = lane >> 2, tg = lane & 3;
    const int dir = blockIdx.y >> 4;
    const int bh = blockIdx.y & 15, b = bh >> 2, h = bh & 3;

    const __half* __restrict__ Qm = dir ? qk1 : qk0;
    const __half* __restrict__ Km = dir ? qk0 : qk1;
    const __half* __restrict__ Vm = dir ? v0m : v1m;
    __half* __restrict__ Om = dir ? m1m : m0m;

    const size_t base = (size_t)b * SEQ * HIDD + (size_t)h * DHEAD;
    const int q0 = blockIdx.x * ATQ + warp * 16;

    const int t8 = lane >> 3, rw = lane & 7;
    const int bRow = ((t8 >> 1) << 3) + rw, bCol = (t8 & 1) << 3;

    // Q fragments resident in registers (4 chunks of k16)
    uint32_t qf[4][4];
#pragma unroll
    for (int kk = 0; kk < 4; kk++) {
        const size_t r0 = base + (size_t)(q0 + g    ) * HIDD + kk * 16;
        const size_t r1 = base + (size_t)(q0 + g + 8) * HIDD + kk * 16;
        qf[kk][0] = *(const uint32_t*)&Qm[r0 + 2*tg    ];
        qf[kk][1] = *(const uint32_t*)&Qm[r1 + 2*tg    ];
        qf[kk][2] = *(const uint32_t*)&Qm[r0 + 2*tg + 8];
        qf[kk][3] = *(const uint32_t*)&Qm[r1 + 2*tg + 8];
    }

    float oa[8][4];
#pragma unroll
    for (int ni = 0; ni < 8; ni++)
#pragma unroll
        for (int r = 0; r < 4; r++) oa[ni][r] = 0.f;
    float ps0 = 0.f, ps1 = 0.f;

    // cp.async slots: row tid>>2, cols (tid&3)*16 + {0,8}
    const int rk = tid >> 2;
    const int ck = (tid & 3) << 4;

    auto load_tile = [&](int t, int buf) {
        const __half* kg = Km + base + (size_t)(t + rk) * HIDD + ck;
        const __half* vg = Vm + base + (size_t)(t + rk) * HIDD + ck;
        __half* ksl = &Ks[buf][rk][ck];
        __half* vsl = &Vs[buf][rk][ck];
        uint32_t d;
        d = (uint32_t)__cvta_generic_to_shared(ksl);     CP16(d, kg);
        d = (uint32_t)__cvta_generic_to_shared(ksl + 8); CP16(d, kg + 8);
        d = (uint32_t)__cvta_generic_to_shared(vsl);     CP16(d, vg);
        d = (uint32_t)__cvta_generic_to_shared(vsl + 8); CP16(d, vg + 8);
        CP_COMMIT();
    };

    load_tile(0, 0);

    const int lr = lane & 15;
    const int lc = (lane >> 4) << 3;

    const int NT = SEQ / ATK;
    for (int it = 0; it < NT; it++) {
        const int buf = it & 1;
        CP_WAIT(0);
        __syncthreads();
        if (it + 1 < NT) load_tile((it + 1) * ATK, buf ^ 1);

        const __half* kb = &Ks[buf][bRow][bCol];     // + np*16*KSTR + kk*16
        const __half* vb = &Vs[buf][lr][lc];         // + ki*16*KSTR + nb*16

        // S = Q @ K^T with pipelined K-fragment loads
        float s[8][4];
#pragma unroll
        for (int ni = 0; ni < 8; ni++)
#pragma unroll
            for (int r = 0; r < 4; r++) s[ni][r] = 0.f;

        uint32_t bc[4], bn[4];
        LDSM4(bc[0], bc[1], bc[2], bc[3],
              (uint32_t)__cvta_generic_to_shared(kb));
#pragma unroll
        for (int kk = 0; kk < 4; kk++) {
#pragma unroll
            for (int np = 0; np < 4; np++) {
                if (!(kk == 3 && np == 3)) {
                    const int nnp = (np < 3) ? np + 1 : 0;
                    const int nkk = (np < 3) ? kk : kk + 1;
                    LDSM4(bn[0], bn[1], bn[2], bn[3],
                          (uint32_t)__cvta_generic_to_shared(
                              kb + nnp * 16 * KSTR + nkk * 16));
                }
                uint32_t bfa[2] = {bc[0], bc[1]}, bfb[2] = {bc[2], bc[3]};
                mma16(s[2*np    ], qf[kk], bfa, s[2*np    ]);
                mma16(s[2*np + 1], qf[kk], bfb, s[2*np + 1]);
                bc[0] = bn[0]; bc[1] = bn[1]; bc[2] = bn[2]; bc[3] = bn[3];
            }
        }

        // hoist first V fragment load — hides LDS latency under exp2 chain
        uint32_t vc[4], vn[4];
        LDSM4T(vc[0], vc[1], vc[2], vc[3],
               (uint32_t)__cvta_generic_to_shared(vb));

        // P = exp2(S); row-sum partials; pack to half2 (frees s regs)
        uint32_t ph[8][2];
#pragma unroll
        for (int ni = 0; ni < 8; ni++) {
            float e0 = exp2f(s[ni][0]);
            float e1 = exp2f(s[ni][1]);
            float e2 = exp2f(s[ni][2]);
            float e3 = exp2f(s[ni][3]);
            ps0 += e0 + e1;
            ps1 += e2 + e3;
            ph[ni][0] = packh2(e0, e1);
            ph[ni][1] = packh2(e2, e3);
        }

        // O += P @ V with pipelined V-fragment loads
#pragma unroll
        for (int ki = 0; ki < 4; ki++) {
            uint32_t af[4];
            af[0] = ph[2*ki    ][0];
            af[1] = ph[2*ki    ][1];
            af[2] = ph[2*ki + 1][0];
            af[3] = ph[2*ki + 1][1];
#pragma unroll
            for (int nb = 0; nb < 4; nb++) {
                if (!(ki == 3 && nb == 3)) {
                    const int nnb = (nb < 3) ? nb + 1 : 0;
                    const int nki = (nb < 3) ? ki : ki + 1;
                    LDSM4T(vn[0], vn[1], vn[2], vn[3],
                           (uint32_t)__cvta_generic_to_shared(
                               vb + nki * 16 * KSTR + nnb * 16));
                }
                uint32_t bfa[2] = {vc[0], vc[1]}, bfb[2] = {vc[2], vc[3]};
                mma16(oa[2*nb    ], af, bfa, oa[2*nb    ]);
                mma16(oa[2*nb + 1], af, bfb, oa[2*nb + 1]);
                vc[0] = vn[0]; vc[1] = vn[1]; vc[2] = vn[2]; vc[3] = vn[3];
            }
        }
    }

    // single end-of-kernel row-sum reduce (quad lanes share a row)
    ps0 += __shfl_xor_sync(0xffffffffu, ps0, 1);
    ps0 += __shfl_xor_sync(0xffffffffu, ps0, 2);
    ps1 += __shfl_xor_sync(0xffffffffu, ps1, 1);
    ps1 += __shfl_xor_sync(0xffffffffu, ps1, 2);
    const float inv0 = 1.f / ps0, inv1 = 1.f / ps1;

#pragma unroll
    for (int ni = 0; ni < 8; ni++) {
        const size_t r0 = base + (size_t)(q0 + g    ) * HIDD + ni * 8 + 2 * tg;
        const size_t r1 = base + (size_t)(q0 + g + 8) * HIDD + ni * 8 + 2 * tg;
        *(uint32_t*)&Om[r0] = packh2(oa[ni][0] * inv0, oa[ni][1] * inv0);
        *(uint32_t*)&Om[r1] = packh2(oa[ni][2] * inv1, oa[ni][3] * inv1);
    }
}

// ---------------------------------------------------------------------------
// LayerNorm (512-wide) + exact GELU. Reads fp32 h, writes fp16 hh.
// ---------------------------------------------------------------------------
__global__ __launch_bounds__(128)
void ln_gelu_kernel(const float* __restrict__ h0, const float* __restrict__ h1,
                    __half* __restrict__ hh0, __half* __restrict__ hh1,
                    const float* __restrict__ gamma, const float* __restrict__ beta)
{
    __shared__ float red[8];
    const int tid = threadIdx.x;
    const size_t row = blockIdx.x;
    const float* __restrict__ h = (row < TOK) ? (h0 + row * 512) : (h1 + (row - TOK) * 512);
    __half* __restrict__ hh = (row < TOK) ? (hh0 + row * 512) : (hh1 + (row - TOK) * 512);

    float4 v = *(const float4*)&h[tid * 4];
    float s  = v.x + v.y + v.z + v.w;
    float ss = v.x*v.x + v.y*v.y + v.z*v.z + v.w*v.w;
#pragma unroll
    for (int o = 16; o > 0; o >>= 1) {
        s  += __shfl_xor_sync(0xffffffffu, s,  o);
        ss += __shfl_xor_sync(0xffffffffu, ss, o);
    }
    const int w = tid >> 5;
    if ((tid & 31) == 0) { red[w] = s; red[4 + w] = ss; }
    __syncthreads();
    s  = red[0] + red[1] + red[2] + red[3];
    ss = red[4] + red[5] + red[6] + red[7];

    const float mu   = s * (1.f / 512.f);
    const float var  = ss * (1.f / 512.f) - mu * mu;
    const float rstd = rsqrtf(var + 1e-5f);

    float4 g4 = *(const float4*)&gamma[tid * 4];
    float4 b4 = *(const float4*)&beta[tid * 4];

    float gin[4] = {v.x, v.y, v.z, v.w};
    float gg[4] = {g4.x, g4.y, g4.z, g4.w};
    float bb[4] = {b4.x, b4.y, b4.z, b4.w};
    float o[4];
#pragma unroll
    for (int i = 0; i < 4; i++) {
        float y = (gin[i] - mu) * rstd * gg[i] + bb[i];
        o[i] = 0.5f * y * (1.f + erff(y * 0.70710678118654752f));
    }
    uint2 u;
    u.x = packh2(o[0], o[1]);
    u.y = packh2(o[2], o[3]);
    *(uint2*)&hh[tid * 4] = u;
}

// ---------------------------------------------------------------------------
// Launch
// ---------------------------------------------------------------------------
extern "C" void kernel_launch(void* const* d_in, const int* in_sizes, int n_in,
                              void* d_out, int out_size)
{
    const float* x0    = (const float*)d_in[0];
    const float* x1    = (const float*)d_in[1];
    const float* Wqk   = (const float*)d_in[2];
    const float* bqk   = (const float*)d_in[3];
    const float* Wv    = (const float*)d_in[4];
    const float* bv    = (const float*)d_in[5];
    const float* Wp    = (const float*)d_in[6];
    const float* bp    = (const float*)d_in[7];
    const float* W1    = (const float*)d_in[8];
    const float* b1    = (const float*)d_in[9];
    const float* gamma = (const float*)d_in[10];
    const float* beta  = (const float*)d_in[11];
    const float* W2    = (const float*)d_in[12];
    const float* b2    = (const float*)d_in[13];

    float* out0 = (float*)d_out;
    float* out1 = out0 + (size_t)TOK * FEATD;

    float* sc = nullptr;
    cudaGetSymbolAddress((void**)&sc, g_scratch);
    __half* hsB = (__half*)sc;

    __half* xh0  = hsB + (size_t)0  * OFS;
    __half* xh1  = hsB + (size_t)1  * OFS;
    __half* qk0  = hsB + (size_t)2  * OFS;
    __half* qk1  = hsB + (size_t)3  * OFS;
    __half* v0   = hsB + (size_t)4  * OFS;
    __half* v1   = hsB + (size_t)5  * OFS;
    __half* m0   = hsB + (size_t)6  * OFS;
    __half* m1   = hsB + (size_t)7  * OFS;
    float*  b1p  = (float*)(hsB + (size_t)8 * OFS);   // 512 floats
    __half* hh0  = hsB + (size_t)10 * OFS;
    __half* hh1  = hsB + (size_t)12 * OFS;
    __half* Wqkh = hsB + (size_t)14 * OFS;     // combined [Wqk;Wv] contiguous
    __half* Wvh  = Wqkh + 65536;
    __half* W2h  = Wvh  + 65536;
    __half* W1h  = W2h  + 131072;              // written by fold_w1
    float* h0 = sc + (size_t)8  * OFS;
    float* h1 = sc + (size_t)11 * OFS;

    cudaFuncSetAttribute(gemm_tc<3,1>, cudaFuncAttributeMaxDynamicSharedMemorySize, GEMM_SMEM);
    cudaFuncSetAttribute(gemm_tc<0,0>, cudaFuncAttributeMaxDynamicSharedMemorySize, GEMM_SMEM);
    cudaFuncSetAttribute(gemm_tc<2,0>, cudaFuncAttributeMaxDynamicSharedMemorySize, GEMM_SMEM);

    // converts + Wp-fold (independent of each other)
    f2h_all<<<4352, 256>>>(x0, x1, Wqk, Wv, W2, xh0, xh1, Wqkh, Wvh, W2h);
    fold_w1<<<64, 256>>>(W1, Wp, bp, b1, W1h, b1p);

    // (DH^-0.5)^0.5 * sqrt(log2 e): softmax runs in exp2 domain
    const float qk_scale = 0.42466087418076f;

    const dim3 g2(2, 2 * TOK / 128);               // (2, 256)
    const dim3 g4(4, 2 * TOK / 128);               // (4, 256)

    // fused QK + V projection: one GEMM, N=512, per-CTA epilogue select
    gemm_tc<3,1><<<g4, 256, GEMM_SMEM>>>(xh0, xh1, xh0, xh1, 256, 256, 256,
                            Wqkh, bqk, bv, nullptr, qk0, qk1, v0, v1,
                            512, 256, qk_scale);

    // Cross attention, both directions
    attn_tc<<<dim3(SEQ / ATQ, 32), 256>>>(qk0, qk1, v0, v1, m0, m1);

    // W1 with concat + folded Wp: A = [xh | m] -> fp32 h  (Wp GEMM eliminated)
    gemm_tc<0,0><<<g4, 256, GEMM_SMEM>>>(xh0, xh1, m0, m1, 256, 256, 256,
                            W1h, b1p, nullptr, nullptr, h0, h1, nullptr, nullptr,
                            512, 512, 1.f);

    ln_gelu_kernel<<<2 * TOK, 128>>>(h0, h1, hh0, hh1, gamma, beta);

    // W2 + residual (fp32 out)
    gemm_tc<2,0><<<g2, 256, GEMM_SMEM>>>(hh0, hh1, hh0, hh1, 512, 512, 512,
                            W2h, b2, x0, x1, out0, out1, nullptr, nullptr,
                            256, 512, 1.f);
}

// round 14
// speedup vs baseline: 1.0060x; 1.0060x over previous
#include <cuda_runtime.h>
#include <cuda_fp16.h>
#include <math.h>
#include <stdint.h>

// Problem constants
#define FEATD 256
#define HIDD  256
#define NHEAD 4
#define DHEAD 64
#define BATCH 4
#define SEQ   2048
#define TOK   (BATCH * SEQ)      // 8192 tokens per stream

// ---------------------------------------------------------------------------
// Scratch
// ---------------------------------------------------------------------------
__device__ float g_scratch[33554432];
#define OFS 2097152               // 8192*256 elements

// ---------------------------------------------------------------------------
// helpers
// ---------------------------------------------------------------------------
__device__ __forceinline__ uint32_t packh2(float a, float b) {
    __half2 h = __floats2half2_rn(a, b);
    return *reinterpret_cast<uint32_t*>(&h);
}

__device__ __forceinline__ void mma16(float d[4], const uint32_t a[4],
                                      const uint32_t b[2], const float c[4]) {
    asm volatile(
        "mma.sync.aligned.m16n8k16.row.col.f32.f16.f16.f32 "
        "{%0,%1,%2,%3},{%4,%5,%6,%7},{%8,%9},{%10,%11,%12,%13};\n"
        : "=f"(d[0]), "=f"(d[1]), "=f"(d[2]), "=f"(d[3])
        : "r"(a[0]), "r"(a[1]), "r"(a[2]), "r"(a[3]),
          "r"(b[0]), "r"(b[1]),
          "f"(c[0]), "f"(c[1]), "f"(c[2]), "f"(c[3]));
}

#define CP16(dst_u32, src_ptr) \
    asm volatile("cp.async.cg.shared.global [%0], [%1], 16;\n" :: "r"(dst_u32), "l"(src_ptr))
#define CP_COMMIT() asm volatile("cp.async.commit_group;\n" ::)
#define CP_WAIT(n)  asm volatile("cp.async.wait_group %0;\n" :: "n"(n))

#define LDSM4(r0, r1, r2, r3, addr) \
    asm volatile("ldmatrix.sync.aligned.m8n8.x4.shared.b16 {%0,%1,%2,%3},[%4];" \
        : "=r"(r0), "=r"(r1), "=r"(r2), "=r"(r3) : "r"(addr))
#define LDSM4T(r0, r1, r2, r3, addr) \
    asm volatile("ldmatrix.sync.aligned.m8n8.x4.trans.shared.b16 {%0,%1,%2,%3},[%4];" \
        : "=r"(r0), "=r"(r1), "=r"(r2), "=r"(r3) : "r"(addr))

// ---------------------------------------------------------------------------
// Fused convert + Wp-fold, ONE launch.
// Blocks [0, 4352): fp32->fp16 convert of x0, x1, Wqk, Wv, W2 (float4 grain).
// Blocks [4352, 4480): fold Wp into W1 (fp32 math):
//   W1m'[n,c] = sum_j W1[n,256+j] * Wp[j*256+c]  -> W1h[n*512+256+c]
//   W1h[n*512+c] = fp16(W1[n*512+c])
//   b1p[n] = b1[n] + sum_j W1[n,256+j] * bp[j]
// Fold j-loop unrolled x8 (8 independent loads in flight: latency/8 — the
// R12/R13 version was MLP~1 and cost ~45us; this is the fix).
// ---------------------------------------------------------------------------
#define NCVT 4352
#define NFOLD 128

__global__ __launch_bounds__(256)
void f2h_fold(const float* __restrict__ x0, const float* __restrict__ x1,
              const float* __restrict__ Wqk, const float* __restrict__ Wv,
              const float* __restrict__ W2,
              const float* __restrict__ W1, const float* __restrict__ Wp,
              const float* __restrict__ bp, const float* __restrict__ b1,
              __half* xh0, __half* xh1, __half* Wqkh, __half* Wvh, __half* W2h,
              __half* __restrict__ W1h, float* __restrict__ b1p)
{
    __shared__ float w1s[4][256];
    __shared__ float red[8][4];
    const int bid = blockIdx.x;

    if (bid < NCVT) {
        int i = bid * 256 + threadIdx.x;
        const float* s; __half* d; int off;
        if      (i < 524288)  { s = x0;  d = xh0;  off = i; }
        else if (i < 1048576) { s = x1;  d = xh1;  off = i - 524288; }
        else if (i < 1064960) { s = Wqk; d = Wqkh; off = i - 1048576; }
        else if (i < 1081344) { s = Wv;  d = Wvh;  off = i - 1064960; }
        else                  { s = W2;  d = W2h;  off = i - 1081344; }
        float4 v = ((const float4*)s)[off];
        uint2 u;
        u.x = packh2(v.x, v.y);
        u.y = packh2(v.z, v.w);
        ((uint2*)d)[off] = u;
        return;
    }

    // ---- fold path: 4 W1-rows per CTA ----
    const int fb = bid - NCVT;            // 0..127
    const int c = threadIdx.x;
    const int n0 = fb * 4;

#pragma unroll
    for (int r = 0; r < 4; r++) {
        const size_t row = (size_t)(n0 + r) * 512;
        W1h[row + c] = __float2half(W1[row + c]);       // lo half pass-through
        w1s[r][c] = W1[row + 256 + c];                  // W1m row
    }
    __syncthreads();

    float pb[4], acc[4];
#pragma unroll
    for (int r = 0; r < 4; r++) { pb[r] = w1s[r][c] * bp[c]; acc[r] = 0.f; }

    for (int j = 0; j < 256; j += 8) {
        float wpv[8];
#pragma unroll
        for (int u = 0; u < 8; u++)
            wpv[u] = Wp[(size_t)(j + u) * 256 + c];     // 8 loads in flight
#pragma unroll
        for (int u = 0; u < 8; u++)
#pragma unroll
            for (int r = 0; r < 4; r++)
                acc[r] = fmaf(w1s[r][j + u], wpv[u], acc[r]);
    }
#pragma unroll
    for (int r = 0; r < 4; r++)
        W1h[(size_t)(n0 + r) * 512 + 256 + c] = __float2half(acc[r]);

    const int lane = c & 31, w = c >> 5;
#pragma unroll
    for (int r = 0; r < 4; r++) {
        float v = pb[r];
#pragma unroll
        for (int o = 16; o > 0; o >>= 1) v += __shfl_xor_sync(0xffffffffu, v, o);
        if (lane == 0) red[w][r] = v;
    }
    __syncthreads();
    if (c < 4) {
        float s = b1[n0 + c];
#pragma unroll
        for (int w2 = 0; w2 < 8; w2++) s += red[w2][c];
        b1p[n0 + c] = s;
    }
}

// ---------------------------------------------------------------------------
// fp16 tensor-core GEMM — simple ldmatrix loop (proven), 3-slot cp.async
// pipeline, BK=32, one barrier per stage.
// MODE 0:+bias  2:+bias+res(fp32 out)  3: fused QKV epilogue.
// ---------------------------------------------------------------------------
#define GSTRH 40
#define GEMM_SMEM (3 * 2 * 128 * GSTRH * 2)

template<int MODE, int OUTH>
__global__ __launch_bounds__(256)
void gemm_tc(const __half* __restrict__ Alo0, const __half* __restrict__ Alo1,
             const __half* __restrict__ Ahi0, const __half* __restrict__ Ahi1,
             int Klo, int lda_lo, int lda_hi,
             const __half* __restrict__ W,
             const float* __restrict__ bias,
             const float* __restrict__ res0, const float* __restrict__ res1,
             void* __restrict__ C0v, void* __restrict__ C1v,
             void* __restrict__ D0v, void* __restrict__ D1v,
             int N, int K, float scale)
{
    extern __shared__ __half hsm[];
    __half* As = hsm;                           // [slot][128][GSTRH]
    __half* Ws = hsm + 3 * 128 * GSTRH;

    const int tid  = threadIdx.x;
    const int warp = tid >> 5, lane = tid & 31;
    const int g = lane >> 2, tg = lane & 3;
    const int wm = warp >> 1, wn = warp & 1;
    const int m0g = blockIdx.y * 128;
    const int stream = (m0g >= TOK) ? 1 : 0;
    const int m0 = m0g - stream * TOK;
    const int n0 = blockIdx.x * 128;

    const __half* __restrict__ Alo = stream ? Alo1 : Alo0;
    const __half* __restrict__ Ahi = stream ? Ahi1 : Ahi0;

    const int rl = tid >> 1;
    const int cl = (tid & 1) << 4;

    const int t8 = lane >> 3, rw = lane & 7;
    const int aRow = ((t8 & 1) << 3) + rw, aCol = (t8 >> 1) << 3;
    const int bRow = ((t8 >> 1) << 3) + rw, bCol = (t8 & 1) << 3;

    const int nst = K / 32;

    auto load_stage = [&](int ks, int slot) {
        const int kbase = ks * 32;
        const __half* Ab; int lda, ka;
        if (kbase < Klo) { Ab = Alo; lda = lda_lo; ka = kbase; }
        else             { Ab = Ahi; lda = lda_hi; ka = kbase - Klo; }
        __half* asl = As + (slot * 128 + rl) * GSTRH + cl;
        __half* wsl = Ws + (slot * 128 + rl) * GSTRH + cl;
        const __half* ag = Ab + (size_t)(m0 + rl) * lda + ka + cl;
        const __half* wg = W + (size_t)(n0 + rl) * K + kbase + cl;
        uint32_t d;
        d = (uint32_t)__cvta_generic_to_shared(asl);     CP16(d, ag);
        d = (uint32_t)__cvta_generic_to_shared(asl + 8); CP16(d, ag + 8);
        d = (uint32_t)__cvta_generic_to_shared(wsl);     CP16(d, wg);
        d = (uint32_t)__cvta_generic_to_shared(wsl + 8); CP16(d, wg + 8);
        CP_COMMIT();
    };

    float acc[2][8][4];
#pragma unroll
    for (int mi = 0; mi < 2; mi++)
#pragma unroll
        for (int ni = 0; ni < 8; ni++)
#pragma unroll
            for (int r = 0; r < 4; r++) acc[mi][ni][r] = 0.f;

    load_stage(0, 0);
    load_stage(1, 1);

    for (int ks = 0; ks < nst; ks++) {
        CP_WAIT(1);
        __syncthreads();
        if (ks + 2 < nst) load_stage(ks + 2, (ks + 2) % 3);
        else              CP_COMMIT();

        const int s = ks % 3;
        const __half* as = As + (size_t)s * 128 * GSTRH;
        const __half* ws = Ws + (size_t)s * 128 * GSTRH;
#pragma unroll
        for (int kk = 0; kk < 2; kk++) {
            const int kb = kk * 16;
            uint32_t af[2][4];
#pragma unroll
            for (int mi = 0; mi < 2; mi++) {
                uint32_t addr = (uint32_t)__cvta_generic_to_shared(
                    &as[(wm * 32 + mi * 16 + aRow) * GSTRH + kb + aCol]);
                LDSM4(af[mi][0], af[mi][1], af[mi][2], af[mi][3], addr);
            }
#pragma unroll
            for (int np = 0; np < 4; np++) {
                uint32_t b0, b1x, b2, b3;
                uint32_t addr = (uint32_t)__cvta_generic_to_shared(
                    &ws[(wn * 64 + np * 16 + bRow) * GSTRH + kb + bCol]);
                LDSM4(b0, b1x, b2, b3, addr);
                uint32_t bfa[2] = {b0, b1x}, bfb[2] = {b2, b3};
#pragma unroll
                for (int mi = 0; mi < 2; mi++) {
                    mma16(acc[mi][2*np    ], af[mi], bfa, acc[mi][2*np    ]);
                    mma16(acc[mi][2*np + 1], af[mi], bfb, acc[mi][2*np + 1]);
                }
            }
        }
    }

    const float* __restrict__ res = stream ? res1 : res0;
    const float* bias_eff = bias;
    float sc_eff = scale;
    __half* Cq = nullptr;
    int nstride = N;
    if (MODE == 3) {
        const int side = (n0 >= 256);
        sc_eff = side ? 1.f : scale;
        bias_eff = side ? (res0 - 256) : bias;     // res0 carries bias2 (bv)
        if (side) Cq = (__half*)((stream ? (__half*)D1v : (__half*)D0v) - 256);
        else      Cq = stream ? (__half*)C1v : (__half*)C0v;
        nstride = 256;
    }

#pragma unroll
    for (int mi = 0; mi < 2; mi++) {
#pragma unroll
        for (int rr = 0; rr < 2; rr++) {
            const int m = m0 + wm * 32 + mi * 16 + g + rr * 8;
#pragma unroll
            for (int ni = 0; ni < 8; ni++) {
                const int c = n0 + wn * 64 + ni * 8 + 2 * tg;
                float2 bb = *(const float2*)&bias_eff[c];
                float v0 = (acc[mi][ni][rr * 2 + 0] + bb.x) * sc_eff;
                float v1 = (acc[mi][ni][rr * 2 + 1] + bb.y) * sc_eff;
                if (MODE == 2) {
                    float2 rv = *(const float2*)&res[(size_t)m * N + c];
                    v0 += rv.x; v1 += rv.y;
                }
                if (MODE == 3) {
                    *(uint32_t*)&Cq[(size_t)m * nstride + c] = packh2(v0, v1);
                } else if (OUTH) {
                    __half* C = stream ? (__half*)C1v : (__half*)C0v;
                    *(uint32_t*)&C[(size_t)m * N + c] = packh2(v0, v1);
                } else {
                    float* C = stream ? (float*)C1v : (float*)C0v;
                    *(float2*)&C[(size_t)m * N + c] = make_float2(v0, v1);
                }
            }
        }
    }
}

// ---------------------------------------------------------------------------
// fp16 tensor-core flash attention — measured 121us @47.6% tensor:
// pipelined K/V fragment loads, hoisted first V ldmatrix over exp2 chain.
// ---------------------------------------------------------------------------
#define ATQ 128
#define ATK 64
#define KSTR 72

__global__ __launch_bounds__(256, 2)
void attn_tc(const __half* __restrict__ qk0, const __half* __restrict__ qk1,
             const __half* __restrict__ v0m, const __half* __restrict__ v1m,
             __half* __restrict__ m0m, __half* __restrict__ m1m)
{
    __shared__ __align__(16) __half Ks[2][ATK][KSTR];
    __shared__ __align__(16) __half Vs[2][ATK][KSTR];

    const int tid  = threadIdx.x;
    const int warp = tid >> 5, lane = tid & 31;
    const int g = lane >> 2, tg = lane & 3;
    const int dir = blockIdx.y >> 4;
    const int bh = blockIdx.y & 15, b = bh >> 2, h = bh & 3;

    const __half* __restrict__ Qm = dir ? qk1 : qk0;
    const __half* __restrict__ Km = dir ? qk0 : qk1;
    const __half* __restrict__ Vm = dir ? v0m : v1m;
    __half* __restrict__ Om = dir ? m1m : m0m;

    const size_t base = (size_t)b * SEQ * HIDD + (size_t)h * DHEAD;
    const int q0 = blockIdx.x * ATQ + warp * 16;

    const int t8 = lane >> 3, rw = lane & 7;
    const int bRow = ((t8 >> 1) << 3) + rw, bCol = (t8 & 1) << 3;

    // Q fragments resident in registers (4 chunks of k16)
    uint32_t qf[4][4];
#pragma unroll
    for (int kk = 0; kk < 4; kk++) {
        const size_t r0 = base + (size_t)(q0 + g    ) * HIDD + kk * 16;
        const size_t r1 = base + (size_t)(q0 + g + 8) * HIDD + kk * 16;
        qf[kk][0] = *(const uint32_t*)&Qm[r0 + 2*tg    ];
        qf[kk][1] = *(const uint32_t*)&Qm[r1 + 2*tg    ];
        qf[kk][2] = *(const uint32_t*)&Qm[r0 + 2*tg + 8];
        qf[kk][3] = *(const uint32_t*)&Qm[r1 + 2*tg + 8];
    }

    float oa[8][4];
#pragma unroll
    for (int ni = 0; ni < 8; ni++)
#pragma unroll
        for (int r = 0; r < 4; r++) oa[ni][r] = 0.f;
    float ps0 = 0.f, ps1 = 0.f;

    // cp.async slots: row tid>>2, cols (tid&3)*16 + {0,8}
    const int rk = tid >> 2;
    const int ck = (tid & 3) << 4;

    auto load_tile = [&](int t, int buf) {
        const __half* kg = Km + base + (size_t)(t + rk) * HIDD + ck;
        const __half* vg = Vm + base + (size_t)(t + rk) * HIDD + ck;
        __half* ksl = &Ks[buf][rk][ck];
        __half* vsl = &Vs[buf][rk][ck];
        uint32_t d;
        d = (uint32_t)__cvta_generic_to_shared(ksl);     CP16(d, kg);
        d = (uint32_t)__cvta_generic_to_shared(ksl + 8); CP16(d, kg + 8);
        d = (uint32_t)__cvta_generic_to_shared(vsl);     CP16(d, vg);
        d = (uint32_t)__cvta_generic_to_shared(vsl + 8); CP16(d, vg + 8);
        CP_COMMIT();
    };

    load_tile(0, 0);

    const int lr = lane & 15;
    const int lc = (lane >> 4) << 3;

    const int NT = SEQ / ATK;
    for (int it = 0; it < NT; it++) {
        const int buf = it & 1;
        CP_WAIT(0);
        __syncthreads();
        if (it + 1 < NT) load_tile((it + 1) * ATK, buf ^ 1);

        const __half* kb = &Ks[buf][bRow][bCol];     // + np*16*KSTR + kk*16
        const __half* vb = &Vs[buf][lr][lc];         // + ki*16*KSTR + nb*16

        // S = Q @ K^T with pipelined K-fragment loads
        float s[8][4];
#pragma unroll
        for (int ni = 0; ni < 8; ni++)
#pragma unroll
            for (int r = 0; r < 4; r++) s[ni][r] = 0.f;

        uint32_t bc[4], bn[4];
        LDSM4(bc[0], bc[1], bc[2], bc[3],
              (uint32_t)__cvta_generic_to_shared(kb));
#pragma unroll
        for (int kk = 0; kk < 4; kk++) {
#pragma unroll
            for (int np = 0; np < 4; np++) {
                if (!(kk == 3 && np == 3)) {
                    const int nnp = (np < 3) ? np + 1 : 0;
                    const int nkk = (np < 3) ? kk : kk + 1;
                    LDSM4(bn[0], bn[1], bn[2], bn[3],
                          (uint32_t)__cvta_generic_to_shared(
                              kb + nnp * 16 * KSTR + nkk * 16));
                }
                uint32_t bfa[2] = {bc[0], bc[1]}, bfb[2] = {bc[2], bc[3]};
                mma16(s[2*np    ], qf[kk], bfa, s[2*np    ]);
                mma16(s[2*np + 1], qf[kk], bfb, s[2*np + 1]);
                bc[0] = bn[0]; bc[1] = bn[1]; bc[2] = bn[2]; bc[3] = bn[3];
            }
        }

        // hoist first V fragment load — hides LDS latency under exp2 chain
        uint32_t vc[4], vn[4];
        LDSM4T(vc[0], vc[1], vc[2], vc[3],
               (uint32_t)__cvta_generic_to_shared(vb));

        // P = exp2(S); row-sum partials; pack to half2 (frees s regs)
        uint32_t ph[8][2];
#pragma unroll
        for (int ni = 0; ni < 8; ni++) {
            float e0 = exp2f(s[ni][0]);
            float e1 = exp2f(s[ni][1]);
            float e2 = exp2f(s[ni][2]);
            float e3 = exp2f(s[ni][3]);
            ps0 += e0 + e1;
            ps1 += e2 + e3;
            ph[ni][0] = packh2(e0, e1);
            ph[ni][1] = packh2(e2, e3);
        }

        // O += P @ V with pipelined V-fragment loads
#pragma unroll
        for (int ki = 0; ki < 4; ki++) {
            uint32_t af[4];
            af[0] = ph[2*ki    ][0];
            af[1] = ph[2*ki    ][1];
            af[2] = ph[2*ki + 1][0];
            af[3] = ph[2*ki + 1][1];
#pragma unroll
            for (int nb = 0; nb < 4; nb++) {
                if (!(ki == 3 && nb == 3)) {
                    const int nnb = (nb < 3) ? nb + 1 : 0;
                    const int nki = (nb < 3) ? ki : ki + 1;
                    LDSM4T(vn[0], vn[1], vn[2], vn[3],
                           (uint32_t)__cvta_generic_to_shared(
                               vb + nki * 16 * KSTR + nnb * 16));
                }
                uint32_t bfa[2] = {vc[0], vc[1]}, bfb[2] = {vc[2], vc[3]};
                mma16(oa[2*nb    ], af, bfa, oa[2*nb    ]);
                mma16(oa[2*nb + 1], af, bfb, oa[2*nb + 1]);
                vc[0] = vn[0]; vc[1] = vn[1]; vc[2] = vn[2]; vc[3] = vn[3];
            }
        }
    }

    // single end-of-kernel row-sum reduce (quad lanes share a row)
    ps0 += __shfl_xor_sync(0xffffffffu, ps0, 1);
    ps0 += __shfl_xor_sync(0xffffffffu, ps0, 2);
    ps1 += __shfl_xor_sync(0xffffffffu, ps1, 1);
    ps1 += __shfl_xor_sync(0xffffffffu, ps1, 2);
    const float inv0 = 1.f / ps0, inv1 = 1.f / ps1;

#pragma unroll
    for (int ni = 0; ni < 8; ni++) {
        const size_t r0 = base + (size_t)(q0 + g    ) * HIDD + ni * 8 + 2 * tg;
        const size_t r1 = base + (size_t)(q0 + g + 8) * HIDD + ni * 8 + 2 * tg;
        *(uint32_t*)&Om[r0] = packh2(oa[ni][0] * inv0, oa[ni][1] * inv0);
        *(uint32_t*)&Om[r1] = packh2(oa[ni][2] * inv1, oa[ni][3] * inv1);
    }
}

// ---------------------------------------------------------------------------
// LayerNorm (512-wide) + exact GELU. Reads fp32 h, writes fp16 hh.
// ---------------------------------------------------------------------------
__global__ __launch_bounds__(128)
void ln_gelu_kernel(const float* __restrict__ h0, const float* __restrict__ h1,
                    __half* __restrict__ hh0, __half* __restrict__ hh1,
                    const float* __restrict__ gamma, const float* __restrict__ beta)
{
    __shared__ float red[8];
    const int tid = threadIdx.x;
    const size_t row = blockIdx.x;
    const float* __restrict__ h = (row < TOK) ? (h0 + row * 512) : (h1 + (row - TOK) * 512);
    __half* __restrict__ hh = (row < TOK) ? (hh0 + row * 512) : (hh1 + (row - TOK) * 512);

    float4 v = *(const float4*)&h[tid * 4];
    float s  = v.x + v.y + v.z + v.w;
    float ss = v.x*v.x + v.y*v.y + v.z*v.z + v.w*v.w;
#pragma unroll
    for (int o = 16; o > 0; o >>= 1) {
        s  += __shfl_xor_sync(0xffffffffu, s,  o);
        ss += __shfl_xor_sync(0xffffffffu, ss, o);
    }
    const int w = tid >> 5;
    if ((tid & 31) == 0) { red[w] = s; red[4 + w] = ss; }
    __syncthreads();
    s  = red[0] + red[1] + red[2] + red[3];
    ss = red[4] + red[5] + red[6] + red[7];

    const float mu   = s * (1.f / 512.f);
    const float var  = ss * (1.f / 512.f) - mu * mu;
    const float rstd = rsqrtf(var + 1e-5f);

    float4 g4 = *(const float4*)&gamma[tid * 4];
    float4 b4 = *(const float4*)&beta[tid * 4];

    float gin[4] = {v.x, v.y, v.z, v.w};
    float gg[4] = {g4.x, g4.y, g4.z, g4.w};
    float bb[4] = {b4.x, b4.y, b4.z, b4.w};
    float o[4];
#pragma unroll
    for (int i = 0; i < 4; i++) {
        float y = (gin[i] - mu) * rstd * gg[i] + bb[i];
        o[i] = 0.5f * y * (1.f + erff(y * 0.70710678118654752f));
    }
    uint2 u;
    u.x = packh2(o[0], o[1]);
    u.y = packh2(o[2], o[3]);
    *(uint2*)&hh[tid * 4] = u;
}

// ---------------------------------------------------------------------------
// Launch
// ---------------------------------------------------------------------------
extern "C" void kernel_launch(void* const* d_in, const int* in_sizes, int n_in,
                              void* d_out, int out_size)
{
    const float* x0    = (const float*)d_in[0];
    const float* x1    = (const float*)d_in[1];
    const float* Wqk   = (const float*)d_in[2];
    const float* bqk   = (const float*)d_in[3];
    const float* Wv    = (const float*)d_in[4];
    const float* bv    = (const float*)d_in[5];
    const float* Wp    = (const float*)d_in[6];
    const float* bp    = (const float*)d_in[7];
    const float* W1    = (const float*)d_in[8];
    const float* b1    = (const float*)d_in[9];
    const float* gamma = (const float*)d_in[10];
    const float* beta  = (const float*)d_in[11];
    const float* W2    = (const float*)d_in[12];
    const float* b2    = (const float*)d_in[13];

    float* out0 = (float*)d_out;
    float* out1 = out0 + (size_t)TOK * FEATD;

    float* sc = nullptr;
    cudaGetSymbolAddress((void**)&sc, g_scratch);
    __half* hsB = (__half*)sc;

    __half* xh0  = hsB + (size_t)0  * OFS;
    __half* xh1  = hsB + (size_t)1  * OFS;
    __half* qk0  = hsB + (size_t)2  * OFS;
    __half* qk1  = hsB + (size_t)3  * OFS;
    __half* v0   = hsB + (size_t)4  * OFS;
    __half* v1   = hsB + (size_t)5  * OFS;
    __half* m0   = hsB + (size_t)6  * OFS;
    __half* m1   = hsB + (size_t)7  * OFS;
    float*  b1p  = (float*)(hsB + (size_t)8 * OFS);   // 512 floats
    __half* hh0  = hsB + (size_t)10 * OFS;
    __half* hh1  = hsB + (size_t)12 * OFS;
    __half* Wqkh = hsB + (size_t)14 * OFS;     // combined [Wqk;Wv] contiguous
    __half* Wvh  = Wqkh + 65536;
    __half* W2h  = Wvh  + 65536;
    __half* W1h  = W2h  + 131072;              // written by fold path
    float* h0 = sc + (size_t)8  * OFS;
    float* h1 = sc + (size_t)11 * OFS;

    cudaFuncSetAttribute(gemm_tc<3,1>, cudaFuncAttributeMaxDynamicSharedMemorySize, GEMM_SMEM);
    cudaFuncSetAttribute(gemm_tc<0,0>, cudaFuncAttributeMaxDynamicSharedMemorySize, GEMM_SMEM);
    cudaFuncSetAttribute(gemm_tc<2,0>, cudaFuncAttributeMaxDynamicSharedMemorySize, GEMM_SMEM);

    // fused converts + Wp-fold, one launch
    f2h_fold<<<NCVT + NFOLD, 256>>>(x0, x1, Wqk, Wv, W2, W1, Wp, bp, b1,
                                    xh0, xh1, Wqkh, Wvh, W2h, W1h, b1p);

    // (DH^-0.5)^0.5 * sqrt(log2 e): softmax runs in exp2 domain
    const float qk_scale = 0.42466087418076f;

    const dim3 g2(2, 2 * TOK / 128);               // (2, 256)
    const dim3 g4(4, 2 * TOK / 128);               // (4, 256)

    // fused QK + V projection: one GEMM, N=512, per-CTA epilogue select
    gemm_tc<3,1><<<g4, 256, GEMM_SMEM>>>(xh0, xh1, xh0, xh1, 256, 256, 256,
                            Wqkh, bqk, bv, nullptr, qk0, qk1, v0, v1,
                            512, 256, qk_scale);

    // Cross attention, both directions
    attn_tc<<<dim3(SEQ / ATQ, 32), 256>>>(qk0, qk1, v0, v1, m0, m1);

    // W1 with concat + folded Wp: A = [xh | m] -> fp32 h  (Wp GEMM eliminated)
    gemm_tc<0,0><<<g4, 256, GEMM_SMEM>>>(xh0, xh1, m0, m1, 256, 256, 256,
                            W1h, b1p, nullptr, nullptr, h0, h1, nullptr, nullptr,
                            512, 512, 1.f);

    ln_gelu_kernel<<<2 * TOK, 128>>>(h0, h1, hh0, hh1, gamma, beta);

    // W2 + residual (fp32 out)
    gemm_tc<2,0><<<g2, 256, GEMM_SMEM>>>(hh0, hh1, hh0, hh1, 512, 512, 512,
                            W2h, b2, x0, x1, out0, out1, nullptr, nullptr,
                            256, 512, 1.f);
}

// round 15
// speedup vs baseline: 1.0203x; 1.0142x over previous
#include <cuda_runtime.h>
#include <cuda_fp16.h>
#include <math.h>
#include <stdint.h>

// Problem constants
#define FEATD 256
#define HIDD  256
#define NHEAD 4
#define DHEAD 64
#define BATCH 4
#define SEQ   2048
#define TOK   (BATCH * SEQ)      // 8192 tokens per stream

// ---------------------------------------------------------------------------
// Scratch
// ---------------------------------------------------------------------------
__device__ float g_scratch[33554432];
#define OFS 2097152               // 8192*256 elements

// ---------------------------------------------------------------------------
// helpers
// ---------------------------------------------------------------------------
__device__ __forceinline__ uint32_t packh2(float a, float b) {
    __half2 h = __floats2half2_rn(a, b);
    return *reinterpret_cast<uint32_t*>(&h);
}

__device__ __forceinline__ void mma16(float d[4], const uint32_t a[4],
                                      const uint32_t b[2], const float c[4]) {
    asm volatile(
        "mma.sync.aligned.m16n8k16.row.col.f32.f16.f16.f32 "
        "{%0,%1,%2,%3},{%4,%5,%6,%7},{%8,%9},{%10,%11,%12,%13};\n"
        : "=f"(d[0]), "=f"(d[1]), "=f"(d[2]), "=f"(d[3])
        : "r"(a[0]), "r"(a[1]), "r"(a[2]), "r"(a[3]),
          "r"(b[0]), "r"(b[1]),
          "f"(c[0]), "f"(c[1]), "f"(c[2]), "f"(c[3]));
}

#define CP16(dst_u32, src_ptr) \
    asm volatile("cp.async.cg.shared.global [%0], [%1], 16;\n" :: "r"(dst_u32), "l"(src_ptr))
#define CP_COMMIT() asm volatile("cp.async.commit_group;\n" ::)
#define CP_WAIT(n)  asm volatile("cp.async.wait_group %0;\n" :: "n"(n))

#define LDSM4(r0, r1, r2, r3, addr) \
    asm volatile("ldmatrix.sync.aligned.m8n8.x4.shared.b16 {%0,%1,%2,%3},[%4];" \
        : "=r"(r0), "=r"(r1), "=r"(r2), "=r"(r3) : "r"(addr))
#define LDSM4T(r0, r1, r2, r3, addr) \
    asm volatile("ldmatrix.sync.aligned.m8n8.x4.trans.shared.b16 {%0,%1,%2,%3},[%4];" \
        : "=r"(r0), "=r"(r1), "=r"(r2), "=r"(r3) : "r"(addr))

// ---------------------------------------------------------------------------
// Fused convert + Wp-fold, ONE launch.
// Blocks [0, 4352): fp32->fp16 convert of x0, x1, Wqk, Wv, W2 (float4 grain).
// Blocks [4352, 4480): fold Wp into W1 (fp32 math, unroll x8 => MLP 8):
//   W1m'[n,c] = sum_j W1[n,256+j] * Wp[j*256+c]  -> W1h[n*512+256+c]
//   W1h[n*512+c] = fp16(W1[n*512+c])
//   b1p[n] = b1[n] + sum_j W1[n,256+j] * bp[j]
// ---------------------------------------------------------------------------
#define NCVT 4352
#define NFOLD 128

__global__ __launch_bounds__(256)
void f2h_fold(const float* __restrict__ x0, const float* __restrict__ x1,
              const float* __restrict__ Wqk, const float* __restrict__ Wv,
              const float* __restrict__ W2,
              const float* __restrict__ W1, const float* __restrict__ Wp,
              const float* __restrict__ bp, const float* __restrict__ b1,
              __half* xh0, __half* xh1, __half* Wqkh, __half* Wvh, __half* W2h,
              __half* __restrict__ W1h, float* __restrict__ b1p)
{
    __shared__ float w1s[4][256];
    __shared__ float red[8][4];
    const int bid = blockIdx.x;

    if (bid < NCVT) {
        int i = bid * 256 + threadIdx.x;
        const float* s; __half* d; int off;
        if      (i < 524288)  { s = x0;  d = xh0;  off = i; }
        else if (i < 1048576) { s = x1;  d = xh1;  off = i - 524288; }
        else if (i < 1064960) { s = Wqk; d = Wqkh; off = i - 1048576; }
        else if (i < 1081344) { s = Wv;  d = Wvh;  off = i - 1064960; }
        else                  { s = W2;  d = W2h;  off = i - 1081344; }
        float4 v = ((const float4*)s)[off];
        uint2 u;
        u.x = packh2(v.x, v.y);
        u.y = packh2(v.z, v.w);
        ((uint2*)d)[off] = u;
        return;
    }

    // ---- fold path: 4 W1-rows per CTA ----
    const int fb = bid - NCVT;            // 0..127
    const int c = threadIdx.x;
    const int n0 = fb * 4;

#pragma unroll
    for (int r = 0; r < 4; r++) {
        const size_t row = (size_t)(n0 + r) * 512;
        W1h[row + c] = __float2half(W1[row + c]);       // lo half pass-through
        w1s[r][c] = W1[row + 256 + c];                  // W1m row
    }
    __syncthreads();

    float pb[4], acc[4];
#pragma unroll
    for (int r = 0; r < 4; r++) { pb[r] = w1s[r][c] * bp[c]; acc[r] = 0.f; }

    for (int j = 0; j < 256; j += 8) {
        float wpv[8];
#pragma unroll
        for (int u = 0; u < 8; u++)
            wpv[u] = Wp[(size_t)(j + u) * 256 + c];     // 8 loads in flight
#pragma unroll
        for (int u = 0; u < 8; u++)
#pragma unroll
            for (int r = 0; r < 4; r++)
                acc[r] = fmaf(w1s[r][j + u], wpv[u], acc[r]);
    }
#pragma unroll
    for (int r = 0; r < 4; r++)
        W1h[(size_t)(n0 + r) * 512 + 256 + c] = __float2half(acc[r]);

    const int lane = c & 31, w = c >> 5;
#pragma unroll
    for (int r = 0; r < 4; r++) {
        float v = pb[r];
#pragma unroll
        for (int o = 16; o > 0; o >>= 1) v += __shfl_xor_sync(0xffffffffu, v, o);
        if (lane == 0) red[w][r] = v;
    }
    __syncthreads();
    if (c < 4) {
        float s = b1[n0 + c];
#pragma unroll
        for (int w2 = 0; w2 < 8; w2++) s += red[w2][c];
        b1p[n0 + c] = s;
    }
}

// ---------------------------------------------------------------------------
// fp16 tensor-core GEMM — R11's proven simple ldmatrix loop.
// 3-slot cp.async pipeline, BK=32, one barrier per stage.
// MODE 0:+bias  2:+bias+res(fp32 out)  3: fused QKV epilogue.
// ---------------------------------------------------------------------------
#define GSTRH 40
#define GEMM_SMEM (3 * 2 * 128 * GSTRH * 2)

template<int MODE, int OUTH>
__global__ __launch_bounds__(256)
void gemm_tc(const __half* __restrict__ Alo0, const __half* __restrict__ Alo1,
             const __half* __restrict__ Ahi0, const __half* __restrict__ Ahi1,
             int Klo, int lda_lo, int lda_hi,
             const __half* __restrict__ W,
             const float* __restrict__ bias,
             const float* __restrict__ res0, const float* __restrict__ res1,
             void* __restrict__ C0v, void* __restrict__ C1v,
             void* __restrict__ D0v, void* __restrict__ D1v,
             int N, int K, float scale)
{
    extern __shared__ __half hsm[];
    __half* As = hsm;                           // [slot][128][GSTRH]
    __half* Ws = hsm + 3 * 128 * GSTRH;

    const int tid  = threadIdx.x;
    const int warp = tid >> 5, lane = tid & 31;
    const int g = lane >> 2, tg = lane & 3;
    const int wm = warp >> 1, wn = warp & 1;
    const int m0g = blockIdx.y * 128;
    const int stream = (m0g >= TOK) ? 1 : 0;
    const int m0 = m0g - stream * TOK;
    const int n0 = blockIdx.x * 128;

    const __half* __restrict__ Alo = stream ? Alo1 : Alo0;
    const __half* __restrict__ Ahi = stream ? Ahi1 : Ahi0;

    const int rl = tid >> 1;
    const int cl = (tid & 1) << 4;

    const int t8 = lane >> 3, rw = lane & 7;
    const int aRow = ((t8 & 1) << 3) + rw, aCol = (t8 >> 1) << 3;
    const int bRow = ((t8 >> 1) << 3) + rw, bCol = (t8 & 1) << 3;

    const int nst = K / 32;

    auto load_stage = [&](int ks, int slot) {
        const int kbase = ks * 32;
        const __half* Ab; int lda, ka;
        if (kbase < Klo) { Ab = Alo; lda = lda_lo; ka = kbase; }
        else             { Ab = Ahi; lda = lda_hi; ka = kbase - Klo; }
        __half* asl = As + (slot * 128 + rl) * GSTRH + cl;
        __half* wsl = Ws + (slot * 128 + rl) * GSTRH + cl;
        const __half* ag = Ab + (size_t)(m0 + rl) * lda + ka + cl;
        const __half* wg = W + (size_t)(n0 + rl) * K + kbase + cl;
        uint32_t d;
        d = (uint32_t)__cvta_generic_to_shared(asl);     CP16(d, ag);
        d = (uint32_t)__cvta_generic_to_shared(asl + 8); CP16(d, ag + 8);
        d = (uint32_t)__cvta_generic_to_shared(wsl);     CP16(d, wg);
        d = (uint32_t)__cvta_generic_to_shared(wsl + 8); CP16(d, wg + 8);
        CP_COMMIT();
    };

    float acc[2][8][4];
#pragma unroll
    for (int mi = 0; mi < 2; mi++)
#pragma unroll
        for (int ni = 0; ni < 8; ni++)
#pragma unroll
            for (int r = 0; r < 4; r++) acc[mi][ni][r] = 0.f;

    load_stage(0, 0);
    load_stage(1, 1);

    for (int ks = 0; ks < nst; ks++) {
        CP_WAIT(1);
        __syncthreads();
        if (ks + 2 < nst) load_stage(ks + 2, (ks + 2) % 3);
        else              CP_COMMIT();

        const int s = ks % 3;
        const __half* as = As + (size_t)s * 128 * GSTRH;
        const __half* ws = Ws + (size_t)s * 128 * GSTRH;
#pragma unroll
        for (int kk = 0; kk < 2; kk++) {
            const int kb = kk * 16;
            uint32_t af[2][4];
#pragma unroll
            for (int mi = 0; mi < 2; mi++) {
                uint32_t addr = (uint32_t)__cvta_generic_to_shared(
                    &as[(wm * 32 + mi * 16 + aRow) * GSTRH + kb + aCol]);
                LDSM4(af[mi][0], af[mi][1], af[mi][2], af[mi][3], addr);
            }
#pragma unroll
            for (int np = 0; np < 4; np++) {
                uint32_t b0, b1x, b2, b3;
                uint32_t addr = (uint32_t)__cvta_generic_to_shared(
                    &ws[(wn * 64 + np * 16 + bRow) * GSTRH + kb + bCol]);
                LDSM4(b0, b1x, b2, b3, addr);
                uint32_t bfa[2] = {b0, b1x}, bfb[2] = {b2, b3};
#pragma unroll
                for (int mi = 0; mi < 2; mi++) {
                    mma16(acc[mi][2*np    ], af[mi], bfa, acc[mi][2*np    ]);
                    mma16(acc[mi][2*np + 1], af[mi], bfb, acc[mi][2*np + 1]);
                }
            }
        }
    }

    const float* __restrict__ res = stream ? res1 : res0;
    const float* bias_eff = bias;
    float sc_eff = scale;
    __half* Cq = nullptr;
    int nstride = N;
    if (MODE == 3) {
        const int side = (n0 >= 256);
        sc_eff = side ? 1.f : scale;
        bias_eff = side ? (res0 - 256) : bias;     // res0 carries bias2 (bv)
        if (side) Cq = (__half*)((stream ? (__half*)D1v : (__half*)D0v) - 256);
        else      Cq = stream ? (__half*)C1v : (__half*)C0v;
        nstride = 256;
    }

#pragma unroll
    for (int mi = 0; mi < 2; mi++) {
#pragma unroll
        for (int rr = 0; rr < 2; rr++) {
            const int m = m0 + wm * 32 + mi * 16 + g + rr * 8;
#pragma unroll
            for (int ni = 0; ni < 8; ni++) {
                const int c = n0 + wn * 64 + ni * 8 + 2 * tg;
                float2 bb = *(const float2*)&bias_eff[c];
                float v0 = (acc[mi][ni][rr * 2 + 0] + bb.x) * sc_eff;
                float v1 = (acc[mi][ni][rr * 2 + 1] + bb.y) * sc_eff;
                if (MODE == 2) {
                    float2 rv = *(const float2*)&res[(size_t)m * N + c];
                    v0 += rv.x; v1 += rv.y;
                }
                if (MODE == 3) {
                    *(uint32_t*)&Cq[(size_t)m * nstride + c] = packh2(v0, v1);
                } else if (OUTH) {
                    __half* C = stream ? (__half*)C1v : (__half*)C0v;
                    *(uint32_t*)&C[(size_t)m * N + c] = packh2(v0, v1);
                } else {
                    float* C = stream ? (float*)C1v : (float*)C0v;
                    *(float2*)&C[(size_t)m * N + c] = make_float2(v0, v1);
                }
            }
        }
    }
}

// ---------------------------------------------------------------------------
// fp16 tensor-core flash attention — R11's EXACT version (the one inside the
// 242.4us best): simple LDSM loops (no fragment pipelining — the R12
// pipelined variant hit the 128-reg cap and regressed ~15us), ph half2 pack,
// launch_bounds(256,2). No-max exp2 softmax.
// ---------------------------------------------------------------------------
#define ATQ 128
#define ATK 64
#define KSTR 72

__global__ __launch_bounds__(256, 2)
void attn_tc(const __half* __restrict__ qk0, const __half* __restrict__ qk1,
             const __half* __restrict__ v0m, const __half* __restrict__ v1m,
             __half* __restrict__ m0m, __half* __restrict__ m1m)
{
    __shared__ __align__(16) __half Ks[2][ATK][KSTR];
    __shared__ __align__(16) __half Vs[2][ATK][KSTR];

    const int tid  = threadIdx.x;
    const int warp = tid >> 5, lane = tid & 31;
    const int g = lane >> 2, tg = lane & 3;
    const int dir = blockIdx.y >> 4;
    const int bh = blockIdx.y & 15, b = bh >> 2, h = bh & 3;

    const __half* __restrict__ Qm = dir ? qk1 : qk0;
    const __half* __restrict__ Km = dir ? qk0 : qk1;
    const __half* __restrict__ Vm = dir ? v0m : v1m;
    __half* __restrict__ Om = dir ? m1m : m0m;

    const size_t base = (size_t)b * SEQ * HIDD + (size_t)h * DHEAD;
    const int q0 = blockIdx.x * ATQ + warp * 16;

    const int t8 = lane >> 3, rw = lane & 7;
    const int bRow = ((t8 >> 1) << 3) + rw, bCol = (t8 & 1) << 3;

    // Q fragments resident in registers (4 chunks of k16)
    uint32_t qf[4][4];
#pragma unroll
    for (int kk = 0; kk < 4; kk++) {
        const size_t r0 = base + (size_t)(q0 + g    ) * HIDD + kk * 16;
        const size_t r1 = base + (size_t)(q0 + g + 8) * HIDD + kk * 16;
        qf[kk][0] = *(const uint32_t*)&Qm[r0 + 2*tg    ];
        qf[kk][1] = *(const uint32_t*)&Qm[r1 + 2*tg    ];
        qf[kk][2] = *(const uint32_t*)&Qm[r0 + 2*tg + 8];
        qf[kk][3] = *(const uint32_t*)&Qm[r1 + 2*tg + 8];
    }

    float oa[8][4];
#pragma unroll
    for (int ni = 0; ni < 8; ni++)
#pragma unroll
        for (int r = 0; r < 4; r++) oa[ni][r] = 0.f;
    float ps0 = 0.f, ps1 = 0.f;      // per-lane partial row sums (rows g, g+8)

    // cp.async slots: row tid>>2, cols (tid&3)*16 + {0,8}
    const int rk = tid >> 2;
    const int ck = (tid & 3) << 4;

    auto load_tile = [&](int t, int buf) {
        const __half* kg = Km + base + (size_t)(t + rk) * HIDD + ck;
        const __half* vg = Vm + base + (size_t)(t + rk) * HIDD + ck;
        __half* ksl = &Ks[buf][rk][ck];
        __half* vsl = &Vs[buf][rk][ck];
        uint32_t d;
        d = (uint32_t)__cvta_generic_to_shared(ksl);     CP16(d, kg);
        d = (uint32_t)__cvta_generic_to_shared(ksl + 8); CP16(d, kg + 8);
        d = (uint32_t)__cvta_generic_to_shared(vsl);     CP16(d, vg);
        d = (uint32_t)__cvta_generic_to_shared(vsl + 8); CP16(d, vg + 8);
        CP_COMMIT();
    };

    load_tile(0, 0);

    const int NT = SEQ / ATK;
    for (int it = 0; it < NT; it++) {
        const int buf = it & 1;
        CP_WAIT(0);
        __syncthreads();
        if (it + 1 < NT) load_tile((it + 1) * ATK, buf ^ 1);

        // S = Q @ K^T  (m16 x n64 per warp, k=64)
        float s[8][4];
#pragma unroll
        for (int ni = 0; ni < 8; ni++)
#pragma unroll
            for (int r = 0; r < 4; r++) s[ni][r] = 0.f;
#pragma unroll
        for (int kk = 0; kk < 4; kk++) {
            const int kb = kk * 16;
#pragma unroll
            for (int np = 0; np < 4; np++) {
                uint32_t b0, b1x, b2, b3;
                uint32_t addr = (uint32_t)__cvta_generic_to_shared(
                    &Ks[buf][np * 16 + bRow][kb + bCol]);
                LDSM4(b0, b1x, b2, b3, addr);
                uint32_t bfa[2] = {b0, b1x}, bfb[2] = {b2, b3};
                mma16(s[2*np    ], qf[kk], bfa, s[2*np    ]);
                mma16(s[2*np + 1], qf[kk], bfb, s[2*np + 1]);
            }
        }

        // P = exp2(S); accumulate row-sum partials and pack to half2
        uint32_t ph[8][2];
#pragma unroll
        for (int ni = 0; ni < 8; ni++) {
            float e0 = exp2f(s[ni][0]);
            float e1 = exp2f(s[ni][1]);
            float e2 = exp2f(s[ni][2]);
            float e3 = exp2f(s[ni][3]);
            ps0 += e0 + e1;
            ps1 += e2 + e3;
            ph[ni][0] = packh2(e0, e1);
            ph[ni][1] = packh2(e2, e3);
        }

        // O += P @ V.  P A-frags are register copies; V via ldmatrix.trans.
        const int lr = lane & 15;
        const int lc = (lane >> 4) << 3;
#pragma unroll
        for (int ki = 0; ki < 4; ki++) {
            uint32_t af[4];
            af[0] = ph[2*ki    ][0];
            af[1] = ph[2*ki    ][1];
            af[2] = ph[2*ki + 1][0];
            af[3] = ph[2*ki + 1][1];
#pragma unroll
            for (int nb = 0; nb < 4; nb++) {
                uint32_t r0, r1, r2, r3;
                uint32_t addr = (uint32_t)__cvta_generic_to_shared(
                    &Vs[buf][ki * 16 + lr][nb * 16 + lc]);
                LDSM4T(r0, r1, r2, r3, addr);
                uint32_t bfa[2] = {r0, r1}, bfb[2] = {r2, r3};
                mma16(oa[2*nb    ], af, bfa, oa[2*nb    ]);
                mma16(oa[2*nb + 1], af, bfb, oa[2*nb + 1]);
            }
        }
    }

    // single end-of-kernel row-sum reduce (quad lanes share a row)
    ps0 += __shfl_xor_sync(0xffffffffu, ps0, 1);
    ps0 += __shfl_xor_sync(0xffffffffu, ps0, 2);
    ps1 += __shfl_xor_sync(0xffffffffu, ps1, 1);
    ps1 += __shfl_xor_sync(0xffffffffu, ps1, 2);
    const float inv0 = 1.f / ps0, inv1 = 1.f / ps1;

#pragma unroll
    for (int ni = 0; ni < 8; ni++) {
        const size_t r0 = base + (size_t)(q0 + g    ) * HIDD + ni * 8 + 2 * tg;
        const size_t r1 = base + (size_t)(q0 + g + 8) * HIDD + ni * 8 + 2 * tg;
        *(uint32_t*)&Om[r0] = packh2(oa[ni][0] * inv0, oa[ni][1] * inv0);
        *(uint32_t*)&Om[r1] = packh2(oa[ni][2] * inv1, oa[ni][3] * inv1);
    }
}

// ---------------------------------------------------------------------------
// LayerNorm (512-wide) + exact GELU. Reads fp32 h, writes fp16 hh.
// ---------------------------------------------------------------------------
__global__ __launch_bounds__(128)
void ln_gelu_kernel(const float* __restrict__ h0, const float* __restrict__ h1,
                    __half* __restrict__ hh0, __half* __restrict__ hh1,
                    const float* __restrict__ gamma, const float* __restrict__ beta)
{
    __shared__ float red[8];
    const int tid = threadIdx.x;
    const size_t row = blockIdx.x;
    const float* __restrict__ h = (row < TOK) ? (h0 + row * 512) : (h1 + (row - TOK) * 512);
    __half* __restrict__ hh = (row < TOK) ? (hh0 + row * 512) : (hh1 + (row - TOK) * 512);

    float4 v = *(const float4*)&h[tid * 4];
    float s  = v.x + v.y + v.z + v.w;
    float ss = v.x*v.x + v.y*v.y + v.z*v.z + v.w*v.w;
#pragma unroll
    for (int o = 16; o > 0; o >>= 1) {
        s  += __shfl_xor_sync(0xffffffffu, s,  o);
        ss += __shfl_xor_sync(0xffffffffu, ss, o);
    }
    const int w = tid >> 5;
    if ((tid & 31) == 0) { red[w] = s; red[4 + w] = ss; }
    __syncthreads();
    s  = red[0] + red[1] + red[2] + red[3];
    ss = red[4] + red[5] + red[6] + red[7];

    const float mu   = s * (1.f / 512.f);
    const float var  = ss * (1.f / 512.f) - mu * mu;
    const float rstd = rsqrtf(var + 1e-5f);

    float4 g4 = *(const float4*)&gamma[tid * 4];
    float4 b4 = *(const float4*)&beta[tid * 4];

    float gin[4] = {v.x, v.y, v.z, v.w};
    float gg[4] = {g4.x, g4.y, g4.z, g4.w};
    float bb[4] = {b4.x, b4.y, b4.z, b4.w};
    float o[4];
#pragma unroll
    for (int i = 0; i < 4; i++) {
        float y = (gin[i] - mu) * rstd * gg[i] + bb[i];
        o[i] = 0.5f * y * (1.f + erff(y * 0.70710678118654752f));
    }
    uint2 u;
    u.x = packh2(o[0], o[1]);
    u.y = packh2(o[2], o[3]);
    *(uint2*)&hh[tid * 4] = u;
}

// ---------------------------------------------------------------------------
// Launch
// ---------------------------------------------------------------------------
extern "C" void kernel_launch(void* const* d_in, const int* in_sizes, int n_in,
                              void* d_out, int out_size)
{
    const float* x0    = (const float*)d_in[0];
    const float* x1    = (const float*)d_in[1];
    const float* Wqk   = (const float*)d_in[2];
    const float* bqk   = (const float*)d_in[3];
    const float* Wv    = (const float*)d_in[4];
    const float* bv    = (const float*)d_in[5];
    const float* Wp    = (const float*)d_in[6];
    const float* bp    = (const float*)d_in[7];
    const float* W1    = (const float*)d_in[8];
    const float* b1    = (const float*)d_in[9];
    const float* gamma = (const float*)d_in[10];
    const float* beta  = (const float*)d_in[11];
    const float* W2    = (const float*)d_in[12];
    const float* b2    = (const float*)d_in[13];

    float* out0 = (float*)d_out;
    float* out1 = out0 + (size_t)TOK * FEATD;

    float* sc = nullptr;
    cudaGetSymbolAddress((void**)&sc, g_scratch);
    __half* hsB = (__half*)sc;

    __half* xh0  = hsB + (size_t)0  * OFS;
    __half* xh1  = hsB + (size_t)1  * OFS;
    __half* qk0  = hsB + (size_t)2  * OFS;
    __half* qk1  = hsB + (size_t)3  * OFS;
    __half* v0   = hsB + (size_t)4  * OFS;
    __half* v1   = hsB + (size_t)5  * OFS;
    __half* m0   = hsB + (size_t)6  * OFS;
    __half* m1   = hsB + (size_t)7  * OFS;
    float*  b1p  = (float*)(hsB + (size_t)8 * OFS);   // 512 floats
    __half* hh0  = hsB + (size_t)10 * OFS;
    __half* hh1  = hsB + (size_t)12 * OFS;
    __half* Wqkh = hsB + (size_t)14 * OFS;     // combined [Wqk;Wv] contiguous
    __half* Wvh  = Wqkh + 65536;
    __half* W2h  = Wvh  + 65536;
    __half* W1h  = W2h  + 131072;              // written by fold path
    float* h0 = sc + (size_t)8  * OFS;
    float* h1 = sc + (size_t)11 * OFS;

    cudaFuncSetAttribute(gemm_tc<3,1>, cudaFuncAttributeMaxDynamicSharedMemorySize, GEMM_SMEM);
    cudaFuncSetAttribute(gemm_tc<0,0>, cudaFuncAttributeMaxDynamicSharedMemorySize, GEMM_SMEM);
    cudaFuncSetAttribute(gemm_tc<2,0>, cudaFuncAttributeMaxDynamicSharedMemorySize, GEMM_SMEM);

    // fused converts + Wp-fold, one launch
    f2h_fold<<<NCVT + NFOLD, 256>>>(x0, x1, Wqk, Wv, W2, W1, Wp, bp, b1,
                                    xh0, xh1, Wqkh, Wvh, W2h, W1h, b1p);

    // (DH^-0.5)^0.5 * sqrt(log2 e): softmax runs in exp2 domain
    const float qk_scale = 0.42466087418076f;

    const dim3 g2(2, 2 * TOK / 128);               // (2, 256)
    const dim3 g4(4, 2 * TOK / 128);               // (4, 256)

    // fused QK + V projection: one GEMM, N=512, per-CTA epilogue select
    gemm_tc<3,1><<<g4, 256, GEMM_SMEM>>>(xh0, xh1, xh0, xh1, 256, 256, 256,
                            Wqkh, bqk, bv, nullptr, qk0, qk1, v0, v1,
                            512, 256, qk_scale);

    // Cross attention, both directions (R11's exact kernel)
    attn_tc<<<dim3(SEQ / ATQ, 32), 256>>>(qk0, qk1, v0, v1, m0, m1);

    // W1 with concat + folded Wp: A = [xh | m] -> fp32 h  (Wp GEMM eliminated)
    gemm_tc<0,0><<<g4, 256, GEMM_SMEM>>>(xh0, xh1, m0, m1, 256, 256, 256,
                            W1h, b1p, nullptr, nullptr, h0, h1, nullptr, nullptr,
                            512, 512, 1.f);

    ln_gelu_kernel<<<2 * TOK, 128>>>(h0, h1, hh0, hh1, gamma, beta);

    // W2 + residual (fp32 out)
    gemm_tc<2,0><<<g2, 256, GEMM_SMEM>>>(hh0, hh1, hh0, hh1, 512, 512, 512,
                            W2h, b2, x0, x1, out0, out1, nullptr, nullptr,
                            256, 512, 1.f);
}

// round 16
// speedup vs baseline: 1.1023x; 1.0804x over previous
#include <cuda_runtime.h>
#include <cuda_fp16.h>
#include <math.h>
#include <stdint.h>

// Problem constants
#define FEATD 256
#define HIDD  256
#define NHEAD 4
#define DHEAD 64
#define BATCH 4
#define SEQ   2048
#define TOK   (BATCH * SEQ)      // 8192 tokens per stream

// ---------------------------------------------------------------------------
// Scratch
// ---------------------------------------------------------------------------
__device__ float g_scratch[33554432];
#define OFS 2097152               // 8192*256 elements

// ---------------------------------------------------------------------------
// helpers
// ---------------------------------------------------------------------------
__device__ __forceinline__ uint32_t packh2(float a, float b) {
    __half2 h = __floats2half2_rn(a, b);
    return *reinterpret_cast<uint32_t*>(&h);
}

__device__ __forceinline__ void mma16(float d[4], const uint32_t a[4],
                                      const uint32_t b[2], const float c[4]) {
    asm volatile(
        "mma.sync.aligned.m16n8k16.row.col.f32.f16.f16.f32 "
        "{%0,%1,%2,%3},{%4,%5,%6,%7},{%8,%9},{%10,%11,%12,%13};\n"
        : "=f"(d[0]), "=f"(d[1]), "=f"(d[2]), "=f"(d[3])
        : "r"(a[0]), "r"(a[1]), "r"(a[2]), "r"(a[3]),
          "r"(b[0]), "r"(b[1]),
          "f"(c[0]), "f"(c[1]), "f"(c[2]), "f"(c[3]));
}

#define CP16(dst_u32, src_ptr) \
    asm volatile("cp.async.cg.shared.global [%0], [%1], 16;\n" :: "r"(dst_u32), "l"(src_ptr))
#define CP_COMMIT() asm volatile("cp.async.commit_group;\n" ::)
#define CP_WAIT(n)  asm volatile("cp.async.wait_group %0;\n" :: "n"(n))

#define LDSM4(r0, r1, r2, r3, addr) \
    asm volatile("ldmatrix.sync.aligned.m8n8.x4.shared.b16 {%0,%1,%2,%3},[%4];" \
        : "=r"(r0), "=r"(r1), "=r"(r2), "=r"(r3) : "r"(addr))
#define LDSM4T(r0, r1, r2, r3, addr) \
    asm volatile("ldmatrix.sync.aligned.m8n8.x4.trans.shared.b16 {%0,%1,%2,%3},[%4];" \
        : "=r"(r0), "=r"(r1), "=r"(r2), "=r"(r3) : "r"(addr))

// ---------------------------------------------------------------------------
// One-shot fp32 -> fp16 conversion of all 7 tensors (single launch) — R11.
// total float4: x0 524288 | x1 524288 | Wqk 16384 | Wv 16384 | Wp 16384 |
//               W1 65536 | W2 32768  => 1196032 = 4672 * 256
// ---------------------------------------------------------------------------
__global__ __launch_bounds__(256)
void f2h_all(const float* __restrict__ x0, const float* __restrict__ x1,
             const float* __restrict__ Wqk, const float* __restrict__ Wv,
             const float* __restrict__ Wp, const float* __restrict__ W1,
             const float* __restrict__ W2,
             __half* xh0, __half* xh1, __half* Wqkh, __half* Wvh,
             __half* Wph, __half* W1h, __half* W2h)
{
    int i = blockIdx.x * 256 + threadIdx.x;
    const float* s; __half* d; int off;
    if      (i < 524288)  { s = x0;  d = xh0;  off = i; }
    else if (i < 1048576) { s = x1;  d = xh1;  off = i - 524288; }
    else if (i < 1064960) { s = Wqk; d = Wqkh; off = i - 1048576; }
    else if (i < 1081344) { s = Wv;  d = Wvh;  off = i - 1064960; }
    else if (i < 1097728) { s = Wp;  d = Wph;  off = i - 1081344; }
    else if (i < 1163264) { s = W1;  d = W1h;  off = i - 1097728; }
    else                  { s = W2;  d = W2h;  off = i - 1163264; }
    float4 v = ((const float4*)s)[off];
    uint2 u;
    u.x = packh2(v.x, v.y);
    u.y = packh2(v.z, v.w);
    ((uint2*)d)[off] = u;
}

// ---------------------------------------------------------------------------
// fp16 tensor-core GEMM — R11's proven simple ldmatrix loop.
// 3-slot cp.async pipeline, BK=32, one barrier per stage.
// MODE 0:+bias(->OUTH)  2:+bias+res(fp32 out)  3: fused QKV epilogue.
// ---------------------------------------------------------------------------
#define GSTRH 40
#define GEMM_SMEM (3 * 2 * 128 * GSTRH * 2)

template<int MODE, int OUTH>
__global__ __launch_bounds__(256)
void gemm_tc(const __half* __restrict__ Alo0, const __half* __restrict__ Alo1,
             const __half* __restrict__ Ahi0, const __half* __restrict__ Ahi1,
             int Klo, int lda_lo, int lda_hi,
             const __half* __restrict__ W,
             const float* __restrict__ bias,
             const float* __restrict__ res0, const float* __restrict__ res1,
             void* __restrict__ C0v, void* __restrict__ C1v,
             void* __restrict__ D0v, void* __restrict__ D1v,
             int N, int K, float scale)
{
    extern __shared__ __half hsm[];
    __half* As = hsm;                           // [slot][128][GSTRH]
    __half* Ws = hsm + 3 * 128 * GSTRH;

    const int tid  = threadIdx.x;
    const int warp = tid >> 5, lane = tid & 31;
    const int g = lane >> 2, tg = lane & 3;
    const int wm = warp >> 1, wn = warp & 1;
    const int m0g = blockIdx.y * 128;
    const int stream = (m0g >= TOK) ? 1 : 0;
    const int m0 = m0g - stream * TOK;
    const int n0 = blockIdx.x * 128;

    const __half* __restrict__ Alo = stream ? Alo1 : Alo0;
    const __half* __restrict__ Ahi = stream ? Ahi1 : Ahi0;

    const int rl = tid >> 1;
    const int cl = (tid & 1) << 4;

    const int t8 = lane >> 3, rw = lane & 7;
    const int aRow = ((t8 & 1) << 3) + rw, aCol = (t8 >> 1) << 3;
    const int bRow = ((t8 >> 1) << 3) + rw, bCol = (t8 & 1) << 3;

    const int nst = K / 32;

    auto load_stage = [&](int ks, int slot) {
        const int kbase = ks * 32;
        const __half* Ab; int lda, ka;
        if (kbase < Klo) { Ab = Alo; lda = lda_lo; ka = kbase; }
        else             { Ab = Ahi; lda = lda_hi; ka = kbase - Klo; }
        __half* asl = As + (slot * 128 + rl) * GSTRH + cl;
        __half* wsl = Ws + (slot * 128 + rl) * GSTRH + cl;
        const __half* ag = Ab + (size_t)(m0 + rl) * lda + ka + cl;
        const __half* wg = W + (size_t)(n0 + rl) * K + kbase + cl;
        uint32_t d;
        d = (uint32_t)__cvta_generic_to_shared(asl);     CP16(d, ag);
        d = (uint32_t)__cvta_generic_to_shared(asl + 8); CP16(d, ag + 8);
        d = (uint32_t)__cvta_generic_to_shared(wsl);     CP16(d, wg);
        d = (uint32_t)__cvta_generic_to_shared(wsl + 8); CP16(d, wg + 8);
        CP_COMMIT();
    };

    float acc[2][8][4];
#pragma unroll
    for (int mi = 0; mi < 2; mi++)
#pragma unroll
        for (int ni = 0; ni < 8; ni++)
#pragma unroll
            for (int r = 0; r < 4; r++) acc[mi][ni][r] = 0.f;

    load_stage(0, 0);
    load_stage(1, 1);

    for (int ks = 0; ks < nst; ks++) {
        CP_WAIT(1);
        __syncthreads();
        if (ks + 2 < nst) load_stage(ks + 2, (ks + 2) % 3);
        else              CP_COMMIT();

        const int s = ks % 3;
        const __half* as = As + (size_t)s * 128 * GSTRH;
        const __half* ws = Ws + (size_t)s * 128 * GSTRH;
#pragma unroll
        for (int kk = 0; kk < 2; kk++) {
            const int kb = kk * 16;
            uint32_t af[2][4];
#pragma unroll
            for (int mi = 0; mi < 2; mi++) {
                uint32_t addr = (uint32_t)__cvta_generic_to_shared(
                    &as[(wm * 32 + mi * 16 + aRow) * GSTRH + kb + aCol]);
                LDSM4(af[mi][0], af[mi][1], af[mi][2], af[mi][3], addr);
            }
#pragma unroll
            for (int np = 0; np < 4; np++) {
                uint32_t b0, b1x, b2, b3;
                uint32_t addr = (uint32_t)__cvta_generic_to_shared(
                    &ws[(wn * 64 + np * 16 + bRow) * GSTRH + kb + bCol]);
                LDSM4(b0, b1x, b2, b3, addr);
                uint32_t bfa[2] = {b0, b1x}, bfb[2] = {b2, b3};
#pragma unroll
                for (int mi = 0; mi < 2; mi++) {
                    mma16(acc[mi][2*np    ], af[mi], bfa, acc[mi][2*np    ]);
                    mma16(acc[mi][2*np + 1], af[mi], bfb, acc[mi][2*np + 1]);
                }
            }
        }
    }

    const float* __restrict__ res = stream ? res1 : res0;
    const float* bias_eff = bias;
    float sc_eff = scale;
    __half* Cq = nullptr;
    int nstride = N;
    if (MODE == 3) {
        const int side = (n0 >= 256);
        sc_eff = side ? 1.f : scale;
        bias_eff = side ? (res0 - 256) : bias;     // res0 carries bias2 (bv)
        if (side) Cq = (__half*)((stream ? (__half*)D1v : (__half*)D0v) - 256);
        else      Cq = stream ? (__half*)C1v : (__half*)C0v;
        nstride = 256;
    }

#pragma unroll
    for (int mi = 0; mi < 2; mi++) {
#pragma unroll
        for (int rr = 0; rr < 2; rr++) {
            const int m = m0 + wm * 32 + mi * 16 + g + rr * 8;
#pragma unroll
            for (int ni = 0; ni < 8; ni++) {
                const int c = n0 + wn * 64 + ni * 8 + 2 * tg;
                float2 bb = *(const float2*)&bias_eff[c];
                float v0 = (acc[mi][ni][rr * 2 + 0] + bb.x) * sc_eff;
                float v1 = (acc[mi][ni][rr * 2 + 1] + bb.y) * sc_eff;
                if (MODE == 2) {
                    float2 rv = *(const float2*)&res[(size_t)m * N + c];
                    v0 += rv.x; v1 += rv.y;
                }
                if (MODE == 3) {
                    *(uint32_t*)&Cq[(size_t)m * nstride + c] = packh2(v0, v1);
                } else if (OUTH) {
                    __half* C = stream ? (__half*)C1v : (__half*)C0v;
                    *(uint32_t*)&C[(size_t)m * N + c] = packh2(v0, v1);
                } else {
                    float* C = stream ? (float*)C1v : (float*)C0v;
                    *(float2*)&C[(size_t)m * N + c] = make_float2(v0, v1);
                }
            }
        }
    }
}

// ---------------------------------------------------------------------------
// fp16 tensor-core flash attention — R11's kernel with ONE delta:
// 3-slot K/V cp.async ring (CP_WAIT(1): each tile load gets ~2 compute
// blocks to land instead of 1). No added fragment registers (R12 lesson).
// Dynamic SMEM: 3 * 64 * 72 * 2 halves * 2 arrays = 55296 B.
// ---------------------------------------------------------------------------
#define ATQ 128
#define ATK 64
#define KSTR 72
#define ATTN_SMEM (3 * ATK * KSTR * 2 * 2)

__global__ __launch_bounds__(256, 2)
void attn_tc(const __half* __restrict__ qk0, const __half* __restrict__ qk1,
             const __half* __restrict__ v0m, const __half* __restrict__ v1m,
             __half* __restrict__ m0m, __half* __restrict__ m1m)
{
    extern __shared__ __half dsm[];
    __half* Ks = dsm;                        // [slot][64][72]
    __half* Vs = dsm + 3 * ATK * KSTR;       // [slot][64][72]

    const int tid  = threadIdx.x;
    const int warp = tid >> 5, lane = tid & 31;
    const int g = lane >> 2, tg = lane & 3;
    const int dir = blockIdx.y >> 4;
    const int bh = blockIdx.y & 15, b = bh >> 2, h = bh & 3;

    const __half* __restrict__ Qm = dir ? qk1 : qk0;
    const __half* __restrict__ Km = dir ? qk0 : qk1;
    const __half* __restrict__ Vm = dir ? v0m : v1m;
    __half* __restrict__ Om = dir ? m1m : m0m;

    const size_t base = (size_t)b * SEQ * HIDD + (size_t)h * DHEAD;
    const int q0 = blockIdx.x * ATQ + warp * 16;

    const int t8 = lane >> 3, rw = lane & 7;
    const int bRow = ((t8 >> 1) << 3) + rw, bCol = (t8 & 1) << 3;

    // Q fragments resident in registers (4 chunks of k16)
    uint32_t qf[4][4];
#pragma unroll
    for (int kk = 0; kk < 4; kk++) {
        const size_t r0 = base + (size_t)(q0 + g    ) * HIDD + kk * 16;
        const size_t r1 = base + (size_t)(q0 + g + 8) * HIDD + kk * 16;
        qf[kk][0] = *(const uint32_t*)&Qm[r0 + 2*tg    ];
        qf[kk][1] = *(const uint32_t*)&Qm[r1 + 2*tg    ];
        qf[kk][2] = *(const uint32_t*)&Qm[r0 + 2*tg + 8];
        qf[kk][3] = *(const uint32_t*)&Qm[r1 + 2*tg + 8];
    }

    float oa[8][4];
#pragma unroll
    for (int ni = 0; ni < 8; ni++)
#pragma unroll
        for (int r = 0; r < 4; r++) oa[ni][r] = 0.f;
    float ps0 = 0.f, ps1 = 0.f;      // per-lane partial row sums (rows g, g+8)

    // cp.async slots: row tid>>2, cols (tid&3)*16 + {0,8}
    const int rk = tid >> 2;
    const int ck = (tid & 3) << 4;

    auto load_tile = [&](int t, int slot) {
        const __half* kg = Km + base + (size_t)(t + rk) * HIDD + ck;
        const __half* vg = Vm + base + (size_t)(t + rk) * HIDD + ck;
        __half* ksl = Ks + (slot * ATK + rk) * KSTR + ck;
        __half* vsl = Vs + (slot * ATK + rk) * KSTR + ck;
        uint32_t d;
        d = (uint32_t)__cvta_generic_to_shared(ksl);     CP16(d, kg);
        d = (uint32_t)__cvta_generic_to_shared(ksl + 8); CP16(d, kg + 8);
        d = (uint32_t)__cvta_generic_to_shared(vsl);     CP16(d, vg);
        d = (uint32_t)__cvta_generic_to_shared(vsl + 8); CP16(d, vg + 8);
        CP_COMMIT();
    };

    load_tile(0, 0);
    load_tile(ATK, 1);

    const int NT = SEQ / ATK;
    for (int it = 0; it < NT; it++) {
        CP_WAIT(1);                  // tile it resident (group id == tile id)
        __syncthreads();             // visibility + slot (it+2)%3 free
        if (it + 2 < NT) load_tile((it + 2) * ATK, (it + 2) % 3);
        else             CP_COMMIT();    // keep group count uniform

        const int sl = it % 3;
        const __half* Kb = Ks + (size_t)sl * ATK * KSTR;
        const __half* Vb = Vs + (size_t)sl * ATK * KSTR;

        // S = Q @ K^T  (m16 x n64 per warp, k=64)
        float s[8][4];
#pragma unroll
        for (int ni = 0; ni < 8; ni++)
#pragma unroll
            for (int r = 0; r < 4; r++) s[ni][r] = 0.f;
#pragma unroll
        for (int kk = 0; kk < 4; kk++) {
            const int kb = kk * 16;
#pragma unroll
            for (int np = 0; np < 4; np++) {
                uint32_t b0, b1x, b2, b3;
                uint32_t addr = (uint32_t)__cvta_generic_to_shared(
                    &Kb[(np * 16 + bRow) * KSTR + kb + bCol]);
                LDSM4(b0, b1x, b2, b3, addr);
                uint32_t bfa[2] = {b0, b1x}, bfb[2] = {b2, b3};
                mma16(s[2*np    ], qf[kk], bfa, s[2*np    ]);
                mma16(s[2*np + 1], qf[kk], bfb, s[2*np + 1]);
            }
        }

        // P = exp2(S); accumulate row-sum partials and pack to half2
        uint32_t ph[8][2];
#pragma unroll
        for (int ni = 0; ni < 8; ni++) {
            float e0 = exp2f(s[ni][0]);
            float e1 = exp2f(s[ni][1]);
            float e2 = exp2f(s[ni][2]);
            float e3 = exp2f(s[ni][3]);
            ps0 += e0 + e1;
            ps1 += e2 + e3;
            ph[ni][0] = packh2(e0, e1);
            ph[ni][1] = packh2(e2, e3);
        }

        // O += P @ V.  P A-frags are register copies; V via ldmatrix.trans.
        const int lr = lane & 15;
        const int lc = (lane >> 4) << 3;
#pragma unroll
        for (int ki = 0; ki < 4; ki++) {
            uint32_t af[4];
            af[0] = ph[2*ki    ][0];
            af[1] = ph[2*ki    ][1];
            af[2] = ph[2*ki + 1][0];
            af[3] = ph[2*ki + 1][1];
#pragma unroll
            for (int nb = 0; nb < 4; nb++) {
                uint32_t r0, r1, r2, r3;
                uint32_t addr = (uint32_t)__cvta_generic_to_shared(
                    &Vb[(ki * 16 + lr) * KSTR + nb * 16 + lc]);
                LDSM4T(r0, r1, r2, r3, addr);
                uint32_t bfa[2] = {r0, r1}, bfb[2] = {r2, r3};
                mma16(oa[2*nb    ], af, bfa, oa[2*nb    ]);
                mma16(oa[2*nb + 1], af, bfb, oa[2*nb + 1]);
            }
        }
    }

    // single end-of-kernel row-sum reduce (quad lanes share a row)
    ps0 += __shfl_xor_sync(0xffffffffu, ps0, 1);
    ps0 += __shfl_xor_sync(0xffffffffu, ps0, 2);
    ps1 += __shfl_xor_sync(0xffffffffu, ps1, 1);
    ps1 += __shfl_xor_sync(0xffffffffu, ps1, 2);
    const float inv0 = 1.f / ps0, inv1 = 1.f / ps1;

#pragma unroll
    for (int ni = 0; ni < 8; ni++) {
        const size_t r0 = base + (size_t)(q0 + g    ) * HIDD + ni * 8 + 2 * tg;
        const size_t r1 = base + (size_t)(q0 + g + 8) * HIDD + ni * 8 + 2 * tg;
        *(uint32_t*)&Om[r0] = packh2(oa[ni][0] * inv0, oa[ni][1] * inv0);
        *(uint32_t*)&Om[r1] = packh2(oa[ni][2] * inv1, oa[ni][3] * inv1);
    }
}

// ---------------------------------------------------------------------------
// LayerNorm (512-wide) + exact GELU. Reads fp32 h, writes fp16 hh.
// ---------------------------------------------------------------------------
__global__ __launch_bounds__(128)
void ln_gelu_kernel(const float* __restrict__ h0, const float* __restrict__ h1,
                    __half* __restrict__ hh0, __half* __restrict__ hh1,
                    const float* __restrict__ gamma, const float* __restrict__ beta)
{
    __shared__ float red[8];
    const int tid = threadIdx.x;
    const size_t row = blockIdx.x;
    const float* __restrict__ h = (row < TOK) ? (h0 + row * 512) : (h1 + (row - TOK) * 512);
    __half* __restrict__ hh = (row < TOK) ? (hh0 + row * 512) : (hh1 + (row - TOK) * 512);

    float4 v = *(const float4*)&h[tid * 4];
    float s  = v.x + v.y + v.z + v.w;
    float ss = v.x*v.x + v.y*v.y + v.z*v.z + v.w*v.w;
#pragma unroll
    for (int o = 16; o > 0; o >>= 1) {
        s  += __shfl_xor_sync(0xffffffffu, s,  o);
        ss += __shfl_xor_sync(0xffffffffu, ss, o);
    }
    const int w = tid >> 5;
    if ((tid & 31) == 0) { red[w] = s; red[4 + w] = ss; }
    __syncthreads();
    s  = red[0] + red[1] + red[2] + red[3];
    ss = red[4] + red[5] + red[6] + red[7];

    const float mu   = s * (1.f / 512.f);
    const float var  = ss * (1.f / 512.f) - mu * mu;
    const float rstd = rsqrtf(var + 1e-5f);

    float4 g4 = *(const float4*)&gamma[tid * 4];
    float4 b4 = *(const float4*)&beta[tid * 4];

    float gin[4] = {v.x, v.y, v.z, v.w};
    float gg[4] = {g4.x, g4.y, g4.z, g4.w};
    float bb[4] = {b4.x, b4.y, b4.z, b4.w};
    float o[4];
#pragma unroll
    for (int i = 0; i < 4; i++) {
        float y = (gin[i] - mu) * rstd * gg[i] + bb[i];
        o[i] = 0.5f * y * (1.f + erff(y * 0.70710678118654752f));
    }
    uint2 u;
    u.x = packh2(o[0], o[1]);
    u.y = packh2(o[2], o[3]);
    *(uint2*)&hh[tid * 4] = u;
}

// ---------------------------------------------------------------------------
// Launch — R11's structure: f2h, Wqkv, attn, Wp, W1(concat x|p), LN, W2.
// ---------------------------------------------------------------------------
extern "C" void kernel_launch(void* const* d_in, const int* in_sizes, int n_in,
                              void* d_out, int out_size)
{
    const float* x0    = (const float*)d_in[0];
    const float* x1    = (const float*)d_in[1];
    const float* Wqk   = (const float*)d_in[2];
    const float* bqk   = (const float*)d_in[3];
    const float* Wv    = (const float*)d_in[4];
    const float* bv    = (const float*)d_in[5];
    const float* Wp    = (const float*)d_in[6];
    const float* bp    = (const float*)d_in[7];
    const float* W1    = (const float*)d_in[8];
    const float* b1    = (const float*)d_in[9];
    const float* gamma = (const float*)d_in[10];
    const float* beta  = (const float*)d_in[11];
    const float* W2    = (const float*)d_in[12];
    const float* b2    = (const float*)d_in[13];

    float* out0 = (float*)d_out;
    float* out1 = out0 + (size_t)TOK * FEATD;

    float* sc = nullptr;
    cudaGetSymbolAddress((void**)&sc, g_scratch);
    __half* hsB = (__half*)sc;

    __half* xh0  = hsB + (size_t)0  * OFS;
    __half* xh1  = hsB + (size_t)1  * OFS;
    __half* qk0  = hsB + (size_t)2  * OFS;
    __half* qk1  = hsB + (size_t)3  * OFS;
    __half* v0   = hsB + (size_t)4  * OFS;
    __half* v1   = hsB + (size_t)5  * OFS;
    __half* m0   = hsB + (size_t)6  * OFS;
    __half* m1   = hsB + (size_t)7  * OFS;
    __half* p0   = hsB + (size_t)8  * OFS;
    __half* p1   = hsB + (size_t)9  * OFS;
    __half* hh0  = hsB + (size_t)10 * OFS;
    __half* hh1  = hsB + (size_t)12 * OFS;
    __half* Wqkh = hsB + (size_t)14 * OFS;     // combined [Wqk;Wv] contiguous
    __half* Wvh  = Wqkh + 65536;
    __half* Wph  = Wvh  + 65536;
    __half* W1h  = Wph  + 65536;
    __half* W2h  = W1h  + 262144;
    float* h0 = sc + (size_t)8  * OFS + 524288;   // avoid p0/p1 (halves 8..10 OFS)
    float* h1 = sc + (size_t)11 * OFS;

    cudaFuncSetAttribute(gemm_tc<3,1>, cudaFuncAttributeMaxDynamicSharedMemorySize, GEMM_SMEM);
    cudaFuncSetAttribute(gemm_tc<0,1>, cudaFuncAttributeMaxDynamicSharedMemorySize, GEMM_SMEM);
    cudaFuncSetAttribute(gemm_tc<0,0>, cudaFuncAttributeMaxDynamicSharedMemorySize, GEMM_SMEM);
    cudaFuncSetAttribute(gemm_tc<2,0>, cudaFuncAttributeMaxDynamicSharedMemorySize, GEMM_SMEM);
    cudaFuncSetAttribute(attn_tc,      cudaFuncAttributeMaxDynamicSharedMemorySize, ATTN_SMEM);

    // all converts in one launch
    f2h_all<<<4672, 256>>>(x0, x1, Wqk, Wv, Wp, W1, W2,
                           xh0, xh1, Wqkh, Wvh, Wph, W1h, W2h);

    // (DH^-0.5)^0.5 * sqrt(log2 e): softmax runs in exp2 domain
    const float qk_scale = 0.42466087418076f;

    const dim3 g2(2, 2 * TOK / 128);               // (2, 256)
    const dim3 g4(4, 2 * TOK / 128);               // (4, 256)

    // fused QK + V projection: one GEMM, N=512, per-CTA epilogue select
    gemm_tc<3,1><<<g4, 256, GEMM_SMEM>>>(xh0, xh1, xh0, xh1, 256, 256, 256,
                            Wqkh, bqk, bv, nullptr, qk0, qk1, v0, v1,
                            512, 256, qk_scale);

    // Cross attention, both directions (3-slot K/V ring)
    attn_tc<<<dim3(SEQ / ATQ, 32), 256, ATTN_SMEM>>>(qk0, qk1, v0, v1, m0, m1);

    // Output projection -> fp16 p
    gemm_tc<0,1><<<g2, 256, GEMM_SMEM>>>(m0, m1, m0, m1, 256, 256, 256,
                            Wph, bp, nullptr, nullptr, p0, p1, nullptr, nullptr,
                            256, 256, 1.f);

    // W1 with concat fused: A = [xh | p] -> fp32 h
    gemm_tc<0,0><<<g4, 256, GEMM_SMEM>>>(xh0, xh1, p0, p1, 256, 256, 256,
                            W1h, b1, nullptr, nullptr, h0, h1, nullptr, nullptr,
                            512, 512, 1.f);

    ln_gelu_kernel<<<2 * TOK, 128>>>(h0, h1, hh0, hh1, gamma, beta);

    // W2 + residual (fp32 out)
    gemm_tc<2,0><<<g2, 256, GEMM_SMEM>>>(hh0, hh1, hh0, hh1, 512, 512, 512,
                            W2h, b2, x0, x1, out0, out1, nullptr, nullptr,
                            256, 512, 1.f);
}